// round 1
// baseline (speedup 1.0000x reference)
#include <cuda_runtime.h>
#include <math.h>

#define BATCH  8
#define N0     4096
#define N1     2048
#define N2     1024
#define FIN    64
#define LATENT 32
#define DEGMAX 128

// ---------------- device scratch (no allocation allowed) ----------------
__device__ int   g_deg[N0];
__device__ int2  g_edge[N0 * DEGMAX];          // .x = col, .y = float bits of val

__device__ float g_xw[BATCH][N0 * 128];        // GEMM outputs (X @ W), max pitch use
__device__ float g_h [BATCH][N0 * 128];        // SpMM outputs level0 (h0, later d2)
__device__ float g_h1[BATCH][N1 * 96];         // level1 features (h1, later d1)
__device__ float g_hl[BATCH][N2 * 64];         // latent GCN output
__device__ float g_z [BATCH][N2 * LATENT];     // reparameterized latent
__device__ float g_d0[BATCH][N2 * 64];         // decoder level2 output
__device__ float g_y [BATCH][N0];              // pooling scores (reused)

__device__ int   g_gidx1[BATCH][N1];           // level1 -> global node id (sorted asc)
__device__ int   g_ginv1[BATCH][N0];           // global -> level1 pos or -1
__device__ float g_gate1[BATCH][N1];           // tanh(y) gates
__device__ int   g_gidx2[BATCH][N2];           // level2 -> global node id
__device__ int   g_lidx2[BATCH][N2];           // level2 -> level1 pos
__device__ int   g_ginv2[BATCH][N0];           // global -> level2 pos or -1
__device__ int   g_linv2[BATCH][N1];           // level1 -> level2 pos or -1
__device__ float g_gate2[BATCH][N2];

// ---------------- ELL build: one warp per row, ballot compaction ----------------
__global__ void build_ell(const float* __restrict__ A0)
{
    int row  = blockIdx.x * (blockDim.x >> 5) + (threadIdx.x >> 5);
    int lane = threadIdx.x & 31;
    if (row >= N0) return;
    const float* arow = A0 + (long)row * N0;
    int base = 0;
    for (int c0 = 0; c0 < N0; c0 += 32) {
        float v = arow[c0 + lane];
        unsigned m = __ballot_sync(0xffffffffu, v != 0.0f);
        if (v != 0.0f) {
            int pos = base + __popc(m & ((1u << lane) - 1u));
            if (pos < DEGMAX) {
                int2 e; e.x = c0 + lane; e.y = __float_as_int(v);
                g_edge[(long)row * DEGMAX + pos] = e;
            }
        }
        base += __popc(m);
    }
    if (lane == 0) g_deg[row] = base < DEGMAX ? base : DEGMAX;
}

// ---------------- generic small GEMM: O[M,C] = gather(A)[M,K] @ W[K,C] ----------------
// gather modes: rowIdxB != null  -> row = rowIdx[r], scaled by rowScale[r] (pool feed)
//               rowInvB != null  -> row = inv[r] if >=0 else zero row     (unpool feed)
__global__ void gemm64(const float* __restrict__ Ab, long sA,
                       const float* __restrict__ W,
                       float* __restrict__ Ob, long sO,
                       int M, int K, int C,
                       const int*   __restrict__ rowIdxB, int sIdx,
                       const float* __restrict__ rowScaleB,
                       const int*   __restrict__ rowInvB,  int sInv)
{
    __shared__ float As[16][64];
    __shared__ float Ws[16][64];

    int b = blockIdx.z;
    const float* A = Ab + (long)b * sA;
    float*       O = Ob + (long)b * sO;

    int tid = threadIdx.x;                   // 256 threads
    int rowTile = blockIdx.y * 64;
    int colTile = blockIdx.x * 64;

    // A-tile load assignment: each thread loads 4 contiguous K elems of one row
    int ar  = tid >> 2;                      // 0..63
    int ak0 = (tid & 3) << 2;                // 0,4,8,12
    int grow = rowTile + ar;

    const float* asrc = nullptr;
    float ascale = 1.0f;
    if (rowIdxB) {
        int src = rowIdxB[(long)b * sIdx + grow];
        asrc   = A + (long)src * K;
        ascale = rowScaleB[(long)b * sIdx + grow];
    } else if (rowInvB) {
        int src = rowInvB[(long)b * sInv + grow];
        asrc = (src >= 0) ? (A + (long)src * K) : nullptr;
    } else {
        asrc = A + (long)grow * K;
    }

    // W-tile load assignment
    int wk = tid >> 4;                       // 0..15
    int wc = (tid & 15) << 2;                // 0..60
    int cc = colTile + wc;

    int tx = tid & 15, ty = tid >> 4;
    float acc[4][4];
#pragma unroll
    for (int i = 0; i < 4; i++)
#pragma unroll
        for (int j = 0; j < 4; j++) acc[i][j] = 0.0f;

    for (int k0 = 0; k0 < K; k0 += 16) {
        float4 av = make_float4(0.f, 0.f, 0.f, 0.f);
        if (asrc) av = *(const float4*)(asrc + k0 + ak0);
        As[ak0 + 0][ar] = av.x * ascale;
        As[ak0 + 1][ar] = av.y * ascale;
        As[ak0 + 2][ar] = av.z * ascale;
        As[ak0 + 3][ar] = av.w * ascale;

        float4 wv = make_float4(0.f, 0.f, 0.f, 0.f);
        if (cc + 3 < C) {
            wv = *(const float4*)(W + (long)(k0 + wk) * C + cc);
        } else {
            if (cc + 0 < C) wv.x = W[(long)(k0 + wk) * C + cc + 0];
            if (cc + 1 < C) wv.y = W[(long)(k0 + wk) * C + cc + 1];
            if (cc + 2 < C) wv.z = W[(long)(k0 + wk) * C + cc + 2];
        }
        Ws[wk][wc + 0] = wv.x;
        Ws[wk][wc + 1] = wv.y;
        Ws[wk][wc + 2] = wv.z;
        Ws[wk][wc + 3] = wv.w;
        __syncthreads();

#pragma unroll
        for (int kk = 0; kk < 16; kk++) {
            float a0 = As[kk][ty * 4 + 0], a1 = As[kk][ty * 4 + 1];
            float a2 = As[kk][ty * 4 + 2], a3 = As[kk][ty * 4 + 3];
            float w0 = Ws[kk][tx * 4 + 0], w1 = Ws[kk][tx * 4 + 1];
            float w2 = Ws[kk][tx * 4 + 2], w3 = Ws[kk][tx * 4 + 3];
            acc[0][0] += a0 * w0; acc[0][1] += a0 * w1; acc[0][2] += a0 * w2; acc[0][3] += a0 * w3;
            acc[1][0] += a1 * w0; acc[1][1] += a1 * w1; acc[1][2] += a1 * w2; acc[1][3] += a1 * w3;
            acc[2][0] += a2 * w0; acc[2][1] += a2 * w1; acc[2][2] += a2 * w2; acc[2][3] += a2 * w3;
            acc[3][0] += a3 * w0; acc[3][1] += a3 * w1; acc[3][2] += a3 * w2; acc[3][3] += a3 * w3;
        }
        __syncthreads();
    }

#pragma unroll
    for (int i = 0; i < 4; i++) {
        int r = rowTile + ty * 4 + i;
#pragma unroll
        for (int j = 0; j < 4; j++) {
            int c = colTile + tx * 4 + j;
            if (c < C) O[(long)r * C + c] = acc[i][j];
        }
    }
}

// ---------------- SpMM over A0's ELL with optional row map + column inverse map --------
// act: 0 none, 1 relu, 2 softplus
__global__ void spmm(const float* __restrict__ Xb, long sX,
                     const float* __restrict__ bias,
                     float* __restrict__ Ob, long sO,
                     int C, int nrows,
                     const int* __restrict__ gidxB, int sG,
                     const int* __restrict__ ginvB,
                     int act)
{
    int b = blockIdx.z;
    const float* X = Xb + (long)b * sX;
    float*       O = Ob + (long)b * sO;
    int r = blockIdx.x * blockDim.y + threadIdx.y;
    if (r >= nrows) return;

    int g = gidxB ? gidxB[(long)b * sG + r] : r;
    const int* ginv = ginvB ? (ginvB + (long)b * N0) : nullptr;

    int deg = g_deg[g];
    const int2* ep = g_edge + (long)g * DEGMAX;
    int c = threadIdx.x;
    float acc = 0.0f;

    for (int e = 0; e < deg; e++) {
        int2 pk = __ldg(ep + e);
        int mc = pk.x;
        float v = __int_as_float(pk.y);
        if (ginv) { mc = __ldg(ginv + mc); if (mc < 0) continue; }
        acc += v * __ldg(X + (long)mc * C + c);
    }
    acc += bias[c];
    if (act == 1)      acc = fmaxf(acc, 0.0f);
    else if (act == 2) acc = fmaxf(acc, 0.0f) + log1pf(expf(-fabsf(acc)));
    O[(long)r * C + c] = acc;
}

// ---------------- pooling scores: y = H @ (p / ||p||) ----------------
__global__ void ykern(const float* __restrict__ Hb, long sH, int C, int n,
                      const float* __restrict__ p, float* __restrict__ yB)
{
    __shared__ float sp[128];
    __shared__ float sinv;
    int tid = threadIdx.x;
    if (tid < C) sp[tid] = p[tid];
    __syncthreads();
    if (tid == 0) {
        float s = 0.0f;
        for (int c = 0; c < C; c++) s += sp[c] * sp[c];
        sinv = rsqrtf(s);
    }
    __syncthreads();

    int b = blockIdx.y;
    const float* H = Hb + (long)b * sH;
    float* y = yB + (long)b * N0;
    int warp = tid >> 5, lane = tid & 31;
    for (int r = blockIdx.x * 4 + warp; r < n; r += gridDim.x * 4) {
        float s = 0.0f;
        for (int c = lane; c < C; c += 32) s += H[(long)r * C + c] * sp[c];
#pragma unroll
        for (int o = 16; o > 0; o >>= 1) s += __shfl_down_sync(0xffffffffu, s, o);
        if (lane == 0) y[r] = s * sinv;
    }
}

// ---------------- exact stable top-k selection + compaction ----------------
// rank_i = #{j : y_j > y_i or (y_j == y_i and j < i)}; keep rank < k (node-order preserved)
template <int IPT>
__global__ __launch_bounds__(1024)
void selectk(const float* __restrict__ yB, int n, int k,
             const int* __restrict__ parentB,          // [b][n] or null (identity)
             int* __restrict__ gidxB, int* __restrict__ lidxB,
             float* __restrict__ gateB,                 // [b][k]
             int* __restrict__ ginvB,                   // [b][N0]
             int* __restrict__ linvB, int linvLen)      // [b][linvLen] or null
{
    extern __shared__ float sy[];
    __shared__ int ssum[1024];
    int b = blockIdx.x;
    const float* y = yB + (long)b * N0;
    int tid = threadIdx.x;

    for (int i = tid; i < n; i += 1024) sy[i] = y[i];
    __syncthreads();

    float myy[IPT];
    int   cnt[IPT];
    int i0 = tid * IPT;
#pragma unroll
    for (int t = 0; t < IPT; t++) { myy[t] = sy[i0 + t]; cnt[t] = 0; }

    for (int j = 0; j < n; j++) {
        float yj = sy[j];
#pragma unroll
        for (int t = 0; t < IPT; t++)
            cnt[t] += (yj > myy[t]) || (yj == myy[t] && j < i0 + t);
    }

    int lsum = 0;
#pragma unroll
    for (int t = 0; t < IPT; t++) lsum += (cnt[t] < k);
    ssum[tid] = lsum;
    __syncthreads();
    // Hillis-Steele inclusive scan over 1024 thread sums
    for (int off = 1; off < 1024; off <<= 1) {
        int v = (tid >= off) ? ssum[tid - off] : 0;
        __syncthreads();
        ssum[tid] += v;
        __syncthreads();
    }
    int base = ssum[tid] - lsum;

    // clear inverse maps
    for (int i = tid; i < N0; i += 1024) ginvB[(long)b * N0 + i] = -1;
    if (linvB) for (int i = tid; i < linvLen; i += 1024) linvB[(long)b * linvLen + i] = -1;
    __syncthreads();

    int pos = base;
#pragma unroll
    for (int t = 0; t < IPT; t++) {
        if (cnt[t] < k) {
            int i = i0 + t;
            int g = parentB ? parentB[(long)b * n + i] : i;
            gidxB[(long)b * k + pos] = g;
            lidxB[(long)b * k + pos] = i;
            gateB[(long)b * k + pos] = tanhf(myy[t]);
            ginvB[(long)b * N0 + g] = pos;
            if (linvB) linvB[(long)b * linvLen + i] = pos;
            pos++;
        }
    }
}

// ---------------- reparameterization + mean/logvar emission ----------------
__global__ void reparam(const float* __restrict__ eps,
                        float* __restrict__ meanOut, float* __restrict__ lvOut)
{
    int idx = blockIdx.x * blockDim.x + threadIdx.x;
    if (idx >= BATCH * N2 * LATENT) return;
    int b  = idx / (N2 * LATENT);
    int rc = idx % (N2 * LATENT);
    int r = rc / LATENT, c = rc % LATENT;
    float m  = g_hl[b][r * 64 + c];
    float lv = g_hl[b][r * 64 + 32 + c];
    meanOut[idx] = m;
    lvOut[idx]   = lv;
    g_z[b][rc]   = m + expf(0.5f * lv) * eps[idx];
}

// ---------------- launch ----------------
extern "C" void kernel_launch(void* const* d_in, const int* in_sizes, int n_in,
                              void* d_out, int out_size)
{
    const float* x    = (const float*)d_in[0];
    const float* eps  = (const float*)d_in[1];
    const float* A0   = (const float*)d_in[2];
    const float* W1   = (const float*)d_in[3];
    const float* b1   = (const float*)d_in[4];
    const float* p1   = (const float*)d_in[5];
    const float* W2   = (const float*)d_in[6];
    const float* b2   = (const float*)d_in[7];
    const float* p2   = (const float*)d_in[8];
    const float* Wlat = (const float*)d_in[9];
    const float* blat = (const float*)d_in[10];
    const float* Wd0  = (const float*)d_in[11];
    const float* bd0  = (const float*)d_in[12];
    const float* Wd1  = (const float*)d_in[13];
    const float* bd1  = (const float*)d_in[14];
    const float* Wd2  = (const float*)d_in[15];
    const float* bd2  = (const float*)d_in[16];
    const float* Wout = (const float*)d_in[17];
    const float* bout = (const float*)d_in[18];

    float* out     = (float*)d_out;
    float* meanOut = out + (long)BATCH * N0 * FIN;
    float* lvOut   = meanOut + (long)BATCH * N2 * LATENT;

    float *xw, *h, *h1, *hl, *z, *d0, *y, *gate1, *gate2;
    int *gidx1, *ginv1, *gidx2, *lidx2, *ginv2, *linv2;
    cudaGetSymbolAddress((void**)&xw,    g_xw);
    cudaGetSymbolAddress((void**)&h,     g_h);
    cudaGetSymbolAddress((void**)&h1,    g_h1);
    cudaGetSymbolAddress((void**)&hl,    g_hl);
    cudaGetSymbolAddress((void**)&z,     g_z);
    cudaGetSymbolAddress((void**)&d0,    g_d0);
    cudaGetSymbolAddress((void**)&y,     g_y);
    cudaGetSymbolAddress((void**)&gidx1, g_gidx1);
    cudaGetSymbolAddress((void**)&ginv1, g_ginv1);
    cudaGetSymbolAddress((void**)&gate1, g_gate1);
    cudaGetSymbolAddress((void**)&gidx2, g_gidx2);
    cudaGetSymbolAddress((void**)&lidx2, g_lidx2);
    cudaGetSymbolAddress((void**)&ginv2, g_ginv2);
    cudaGetSymbolAddress((void**)&linv2, g_linv2);
    cudaGetSymbolAddress((void**)&gate2, g_gate2);

    const long SXW = (long)N0 * 128;
    const long SH  = (long)N0 * 128;
    const long SH1 = (long)N1 * 96;
    const long SHL = (long)N2 * 64;
    const long SZ  = (long)N2 * LATENT;
    const long SD0 = (long)N2 * 64;

    // 0. sparsify A0 (ELL)
    build_ell<<<N0 / 8, 256>>>(A0);

    // 1. encoder GCN1: t = x @ W1 ; h0 = relu(A0 @ t + b1)
    gemm64<<<dim3(2, N0 / 64, BATCH), 256>>>(x, (long)N0 * FIN, W1, xw, SXW,
                                             N0, FIN, 128, nullptr, 0, nullptr, nullptr, 0);
    spmm<<<dim3(N0 / 4, 1, BATCH), dim3(128, 4)>>>(xw, SXW, b1, h, SH, 128, N0,
                                                   nullptr, 0, nullptr, 1);

    // 2. pool1
    ykern<<<dim3(256, BATCH), 128>>>(h, SH, 128, N0, p1, y);
    selectk<4><<<BATCH, 1024, N0 * sizeof(float)>>>(y, N0, N1, nullptr,
                                                    gidx1, gidx1, gate1, ginv1, nullptr, 0);

    // 3. encoder GCN2 on gated pooled features
    gemm64<<<dim3(1, N1 / 64, BATCH), 256>>>(h, SH, W2, xw, SXW,
                                             N1, 128, 64, gidx1, N1, gate1, nullptr, 0);
    spmm<<<dim3(N1 / 4, 1, BATCH), dim3(64, 4)>>>(xw, SXW, b2, h1, SH1, 64, N1,
                                                  gidx1, N1, ginv1, 1);

    // 4. pool2 (composed with level1 ids)
    ykern<<<dim3(256, BATCH), 128>>>(h1, SH1, 64, N1, p2, y);
    selectk<2><<<BATCH, 1024, N1 * sizeof(float)>>>(y, N1, N2, gidx1,
                                                    gidx2, lidx2, gate2, ginv2, linv2, N1);

    // 5. latent GCN (no activation)
    gemm64<<<dim3(1, N2 / 64, BATCH), 256>>>(h1, SH1, Wlat, xw, SXW,
                                             N2, 64, 64, lidx2, N2, gate2, nullptr, 0);
    spmm<<<dim3(N2 / 4, 1, BATCH), dim3(64, 4)>>>(xw, SXW, blat, hl, SHL, 64, N2,
                                                  gidx2, N2, ginv2, 0);

    // 6. reparameterize; emit mean/logvar
    reparam<<<(BATCH * N2 * LATENT + 255) / 256, 256>>>(eps, meanOut, lvOut);

    // 7. decoder GCN0 at level2
    gemm64<<<dim3(1, N2 / 64, BATCH), 256>>>(z, SZ, Wd0, xw, SXW,
                                             N2, 32, 64, nullptr, 0, nullptr, nullptr, 0);
    spmm<<<dim3(N2 / 4, 1, BATCH), dim3(64, 4)>>>(xw, SXW, bd0, d0, SD0, 64, N2,
                                                  gidx2, N2, ginv2, 1);

    // 8. unpool->level1, decoder GCN1
    gemm64<<<dim3(2, N1 / 64, BATCH), 256>>>(d0, SD0, Wd1, xw, SXW,
                                             N1, 64, 96, nullptr, 0, nullptr, linv2, N1);
    spmm<<<dim3(N1 / 4, 1, BATCH), dim3(96, 4)>>>(xw, SXW, bd1, h1, SH1, 96, N1,
                                                  gidx1, N1, ginv1, 1);

    // 9. unpool->level0, decoder GCN2
    gemm64<<<dim3(2, N0 / 64, BATCH), 256>>>(h1, SH1, Wd2, xw, SXW,
                                             N0, 96, 128, nullptr, 0, nullptr, ginv1, N0);
    spmm<<<dim3(N0 / 4, 1, BATCH), dim3(128, 4)>>>(xw, SXW, bd2, h, SH, 128, N0,
                                                   nullptr, 0, nullptr, 1);

    // 10. output GCN + softplus, straight into d_out
    gemm64<<<dim3(1, N0 / 64, BATCH), 256>>>(h, SH, Wout, xw, SXW,
                                             N0, 128, 64, nullptr, 0, nullptr, nullptr, 0);
    spmm<<<dim3(N0 / 4, 1, BATCH), dim3(64, 4)>>>(xw, SXW, bout, out, (long)N0 * FIN, 64, N0,
                                                  nullptr, 0, nullptr, 2);
}

// round 2
// speedup vs baseline: 2.7934x; 2.7934x over previous
#include <cuda_runtime.h>
#include <math.h>

#define BATCH  8
#define N0     4096
#define N1     2048
#define N2     1024
#define FIN    64
#define LATENT 32
#define DEGMAX 128

// ---------------- device scratch ----------------
__device__ int   g_deg[N0];
__device__ int2  g_edge[N0 * DEGMAX];

__device__ int   g_deg1[BATCH * N1];
__device__ int2  g_edge1[BATCH * N1 * DEGMAX];
__device__ int   g_deg2[BATCH * N2];
__device__ int2  g_edge2[BATCH * N2 * DEGMAX];

__device__ float g_xw[BATCH][N0 * 128];
__device__ float g_h [BATCH][N0 * 128];
__device__ float g_h1[BATCH][N1 * 96];
__device__ float g_hl[BATCH][N2 * 64];
__device__ float g_z [BATCH][N2 * LATENT];
__device__ float g_d0[BATCH][N2 * 64];
__device__ float g_y [BATCH][N0];
__device__ int   g_cnt[BATCH][N0];

__device__ int   g_gidx1[BATCH][N1];
__device__ int   g_ginv1[BATCH][N0];
__device__ float g_gate1[BATCH][N1];
__device__ int   g_gidx2[BATCH][N2];
__device__ int   g_lidx2[BATCH][N2];
__device__ int   g_ginv2[BATCH][N0];
__device__ int   g_linv2[BATCH][N1];
__device__ float g_gate2[BATCH][N2];

// ---------------- ELL build ----------------
__global__ void build_ell(const float* __restrict__ A0)
{
    int row  = blockIdx.x * (blockDim.x >> 5) + (threadIdx.x >> 5);
    int lane = threadIdx.x & 31;
    if (row >= N0) return;
    const float* arow = A0 + (long)row * N0;
    int base = 0;
    for (int c0 = 0; c0 < N0; c0 += 32) {
        float v = arow[c0 + lane];
        unsigned m = __ballot_sync(0xffffffffu, v != 0.0f);
        if (v != 0.0f) {
            int pos = base + __popc(m & ((1u << lane) - 1u));
            if (pos < DEGMAX) {
                int2 e; e.x = c0 + lane; e.y = __float_as_int(v);
                g_edge[(long)row * DEGMAX + pos] = e;
            }
        }
        base += __popc(m);
    }
    if (lane == 0) g_deg[row] = base < DEGMAX ? base : DEGMAX;
}

// ---------------- sub-ELL build (remap parent edges through inverse map) -------
__global__ void build_sub(const int2* __restrict__ srcEdge, long seStride,
                          const int* __restrict__ srcDeg, long sdStride,
                          const int* __restrict__ rowMapB, long sMap,
                          const int* __restrict__ invB, long sInv,
                          int2* __restrict__ dstEdge, int* __restrict__ dstDeg,
                          int nrows)
{
    int b = blockIdx.y;
    int r = blockIdx.x * (blockDim.x >> 5) + (threadIdx.x >> 5);
    int lane = threadIdx.x & 31;
    if (r >= nrows) return;
    int src = rowMapB[(long)b * sMap + r];
    const int2* ep = srcEdge + (long)b * seStride + (long)src * DEGMAX;
    int deg = srcDeg[(long)b * sdStride + src];
    const int* inv = invB + (long)b * sInv;
    int2* op = dstEdge + ((long)b * nrows + r) * DEGMAX;
    int base = 0;
    for (int c0 = 0; c0 < deg; c0 += 32) {
        int e = c0 + lane;
        int mc = -1; int2 pk;
        if (e < deg) { pk = __ldg(ep + e); mc = __ldg(inv + pk.x); }
        unsigned m = __ballot_sync(0xffffffffu, mc >= 0);
        if (mc >= 0) {
            int pos = base + __popc(m & ((1u << lane) - 1u));
            int2 o; o.x = mc; o.y = pk.y;
            op[pos] = o;
        }
        base += __popc(m);
    }
    if (lane == 0) dstDeg[(long)b * nrows + r] = base;
}

// ---------------- GEMM: 128x64 tile, 8x4 per thread, float4 smem -------------
// MODE 0: plain rows   MODE 1: gather rows (map) * scale   MODE 2: inv rows (-1 -> zero)
template<int K, int C, int MODE>
__global__ __launch_bounds__(256)
void gemmT(const float* __restrict__ Ab, long sA,
           const float* __restrict__ W,
           float* __restrict__ Ob, long sO,
           const int* __restrict__ mapB, long sMap,
           const float* __restrict__ scaleB)
{
    __shared__ float As[32][128];
    __shared__ float Ws[32][64];

    int b = blockIdx.z;
    const float* A = Ab + (long)b * sA;
    float*       O = Ob + (long)b * sO;
    int tid = threadIdx.x;
    int rowTile = blockIdx.y * 128;
    int colTile = blockIdx.x * 64;

    // A loader: 2 threads per row, 16 k each
    int lr = tid >> 1;
    int lk = (tid & 1) * 16;
    int grow = rowTile + lr;
    const float* asrc;
    float ascale = 1.0f;
    if (MODE == 0) {
        asrc = A + (long)grow * K;
    } else if (MODE == 1) {
        int s = mapB[(long)b * sMap + grow];
        asrc = A + (long)s * K;
        ascale = scaleB[(long)b * sMap + grow];
    } else {
        int s = mapB[(long)b * sMap + grow];
        asrc = (s >= 0) ? (A + (long)s * K) : nullptr;
    }

    // W loader: 8 threads per k-row, 8 cols each
    int wr  = tid >> 3;
    int wc0 = (tid & 7) * 8;

    int ry = tid >> 4, rx = tid & 15;
    float acc[8][4];
#pragma unroll
    for (int i = 0; i < 8; i++)
#pragma unroll
        for (int j = 0; j < 4; j++) acc[i][j] = 0.0f;

    for (int kt = 0; kt < K; kt += 32) {
#pragma unroll
        for (int t = 0; t < 16; t += 4) {
            float4 v = asrc ? *(const float4*)(asrc + kt + lk + t)
                            : make_float4(0.f, 0.f, 0.f, 0.f);
            As[lk + t + 0][lr] = v.x * ascale;
            As[lk + t + 1][lr] = v.y * ascale;
            As[lk + t + 2][lr] = v.z * ascale;
            As[lk + t + 3][lr] = v.w * ascale;
        }
#pragma unroll
        for (int t = 0; t < 8; t += 4) {
            int cc = colTile + wc0 + t;
            float4 v = (cc < C) ? *(const float4*)(W + (long)(kt + wr) * C + cc)
                                : make_float4(0.f, 0.f, 0.f, 0.f);
            *(float4*)&Ws[wr][wc0 + t] = v;
        }
        __syncthreads();

#pragma unroll
        for (int kk = 0; kk < 32; kk++) {
            float4 a0 = *(const float4*)(&As[kk][ry * 8]);
            float4 a1 = *(const float4*)(&As[kk][ry * 8 + 4]);
            float4 w  = *(const float4*)(&Ws[kk][rx * 4]);
            acc[0][0] += a0.x * w.x; acc[0][1] += a0.x * w.y; acc[0][2] += a0.x * w.z; acc[0][3] += a0.x * w.w;
            acc[1][0] += a0.y * w.x; acc[1][1] += a0.y * w.y; acc[1][2] += a0.y * w.z; acc[1][3] += a0.y * w.w;
            acc[2][0] += a0.z * w.x; acc[2][1] += a0.z * w.y; acc[2][2] += a0.z * w.z; acc[2][3] += a0.z * w.w;
            acc[3][0] += a0.w * w.x; acc[3][1] += a0.w * w.y; acc[3][2] += a0.w * w.z; acc[3][3] += a0.w * w.w;
            acc[4][0] += a1.x * w.x; acc[4][1] += a1.x * w.y; acc[4][2] += a1.x * w.z; acc[4][3] += a1.x * w.w;
            acc[5][0] += a1.y * w.x; acc[5][1] += a1.y * w.y; acc[5][2] += a1.y * w.z; acc[5][3] += a1.y * w.w;
            acc[6][0] += a1.z * w.x; acc[6][1] += a1.z * w.y; acc[6][2] += a1.z * w.z; acc[6][3] += a1.z * w.w;
            acc[7][0] += a1.w * w.x; acc[7][1] += a1.w * w.y; acc[7][2] += a1.w * w.z; acc[7][3] += a1.w * w.w;
        }
        __syncthreads();
    }

    int cc = colTile + rx * 4;
    if (cc < C) {
#pragma unroll
        for (int i = 0; i < 8; i++) {
            long r = rowTile + ry * 8 + i;
            *(float4*)(O + r * C + cc) =
                make_float4(acc[i][0], acc[i][1], acc[i][2], acc[i][3]);
        }
    }
}

// ---------------- SpMM (single-hop ELL) + optional fused pooling score --------
// act: 0 none, 1 relu, 2 softplus
template<int C, int RPB>
__global__ void spmmT(const int2* __restrict__ edgeB, long eStride,
                      const int*  __restrict__ degB,  long dStride,
                      const float* __restrict__ Xb, long sX,
                      const float* __restrict__ bias,
                      float* __restrict__ Ob, long sO,
                      int act,
                      const float* __restrict__ p, float* __restrict__ yB)
{
    __shared__ float sp[C];
    __shared__ float sred[RPB][C / 32];

    int b = blockIdx.z;
    const float* X = Xb + (long)b * sX;
    float*       O = Ob + (long)b * sO;
    int tx = threadIdx.x, ty = threadIdx.y;
    int tid = ty * C + tx;
    int r = blockIdx.x * RPB + ty;

    if (p) {
        for (int t = tid; t < C; t += C * RPB) sp[t] = p[t];
        __syncthreads();
    }

    int deg = degB[(long)b * dStride + r];
    const int2* ep = edgeB + (long)b * eStride + (long)r * DEGMAX;
    float acc = 0.0f;
#pragma unroll 4
    for (int e = 0; e < deg; e++) {
        int2 pk = __ldg(ep + e);
        acc += __int_as_float(pk.y) * __ldg(X + (long)pk.x * C + tx);
    }
    acc += bias[tx];
    if (act == 1)      acc = fmaxf(acc, 0.0f);
    else if (act == 2) acc = fmaxf(acc, 0.0f) + log1pf(expf(-fabsf(acc)));
    O[(long)r * C + tx] = acc;

    if (p) {
        float d = acc * sp[tx];
#pragma unroll
        for (int o = 16; o > 0; o >>= 1) d += __shfl_down_sync(0xffffffffu, d, o);
        if ((tx & 31) == 0) sred[ty][tx >> 5] = d;
        __syncthreads();
        if (tx == 0) {
            float s = 0.0f;
#pragma unroll
            for (int w = 0; w < C / 32; w++) s += sred[ty][w];
            yB[(long)b * N0 + r] = s;   // un-normalized; rank-invariant (1/||p|| > 0)
        }
    }
}

// ---------------- wide parallel rank counting ----------------
__global__ void rankk(const float* __restrict__ yB, int n, int* __restrict__ cntB)
{
    __shared__ float sj[1024];
    int b = blockIdx.z;
    const float* y = yB + (long)b * N0;
    int i = blockIdx.x * 256 + threadIdx.x;
    float yi = y[i];
    int j0 = blockIdx.y * 1024;
    for (int t = threadIdx.x; t < 1024; t += 256) sj[t] = y[j0 + t];
    __syncthreads();
    int c = 0;
#pragma unroll 8
    for (int t = 0; t < 1024; t++) {
        float yj = sj[t];
        int j = j0 + t;
        c += (yj > yi) || (yj == yi && j < i);
    }
    atomicAdd(&cntB[(long)b * N0 + i], c);
}

// ---------------- compaction (keep rank < k, node order preserved) ------------
template<int IPT>
__global__ __launch_bounds__(1024)
void compactk(const int* __restrict__ cntB, const float* __restrict__ yB,
              int n, int k,
              const float* __restrict__ p, int Cp,
              const int* __restrict__ parentB, long sPar,
              int* __restrict__ gidxB, int* __restrict__ lidxB,
              float* __restrict__ gateB,
              int* __restrict__ ginvB,
              int* __restrict__ linvB, int linvLen)
{
    __shared__ int ssum[1024];
    __shared__ float srn;
    int b = blockIdx.x, tid = threadIdx.x;
    if (tid == 0) {
        float s = 0.0f;
        for (int c = 0; c < Cp; c++) { float v = p[c]; s += v * v; }
        srn = rsqrtf(s);
    }

    int i0 = tid * IPT;
    int keep[IPT];
    int lsum = 0;
#pragma unroll
    for (int t = 0; t < IPT; t++) {
        keep[t] = cntB[(long)b * N0 + i0 + t] < k;
        lsum += keep[t];
    }
    ssum[tid] = lsum;
    __syncthreads();
    for (int off = 1; off < 1024; off <<= 1) {
        int v = (tid >= off) ? ssum[tid - off] : 0;
        __syncthreads();
        ssum[tid] += v;
        __syncthreads();
    }
    int base = ssum[tid] - lsum;

    for (int i = tid; i < N0; i += 1024) ginvB[(long)b * N0 + i] = -1;
    if (linvB) for (int i = tid; i < linvLen; i += 1024) linvB[(long)b * linvLen + i] = -1;
    __syncthreads();

    float rn = srn;
    int pos = base;
#pragma unroll
    for (int t = 0; t < IPT; t++) {
        if (keep[t]) {
            int i = i0 + t;
            int g = parentB ? parentB[(long)b * sPar + i] : i;
            gidxB[(long)b * k + pos] = g;
            lidxB[(long)b * k + pos] = i;
            gateB[(long)b * k + pos] = tanhf(yB[(long)b * N0 + i] * rn);
            ginvB[(long)b * N0 + g] = pos;
            if (linvB) linvB[(long)b * linvLen + i] = pos;
            pos++;
        }
    }
}

// ---------------- reparameterization ----------------
__global__ void reparam(const float* __restrict__ eps,
                        float* __restrict__ meanOut, float* __restrict__ lvOut)
{
    int idx = blockIdx.x * blockDim.x + threadIdx.x;
    if (idx >= BATCH * N2 * LATENT) return;
    int b  = idx / (N2 * LATENT);
    int rc = idx % (N2 * LATENT);
    int r = rc / LATENT, c = rc % LATENT;
    float m  = g_hl[b][r * 64 + c];
    float lv = g_hl[b][r * 64 + 32 + c];
    meanOut[idx] = m;
    lvOut[idx]   = lv;
    g_z[b][rc]   = m + expf(0.5f * lv) * eps[idx];
}

// ---------------- launch ----------------
extern "C" void kernel_launch(void* const* d_in, const int* in_sizes, int n_in,
                              void* d_out, int out_size)
{
    const float* x    = (const float*)d_in[0];
    const float* eps  = (const float*)d_in[1];
    const float* A0   = (const float*)d_in[2];
    const float* W1   = (const float*)d_in[3];
    const float* b1   = (const float*)d_in[4];
    const float* p1   = (const float*)d_in[5];
    const float* W2   = (const float*)d_in[6];
    const float* b2   = (const float*)d_in[7];
    const float* p2   = (const float*)d_in[8];
    const float* Wlat = (const float*)d_in[9];
    const float* blat = (const float*)d_in[10];
    const float* Wd0  = (const float*)d_in[11];
    const float* bd0  = (const float*)d_in[12];
    const float* Wd1  = (const float*)d_in[13];
    const float* bd1  = (const float*)d_in[14];
    const float* Wd2  = (const float*)d_in[15];
    const float* bd2  = (const float*)d_in[16];
    const float* Wout = (const float*)d_in[17];
    const float* bout = (const float*)d_in[18];

    float* out     = (float*)d_out;
    float* meanOut = out + (long)BATCH * N0 * FIN;
    float* lvOut   = meanOut + (long)BATCH * N2 * LATENT;

    float *xw, *h, *h1, *hl, *z, *d0, *y, *gate1, *gate2;
    int *gidx1, *ginv1, *gidx2, *lidx2, *ginv2, *linv2, *cnt;
    int2 *edge1, *edge2;
    int *deg1, *deg2;
    cudaGetSymbolAddress((void**)&xw,    g_xw);
    cudaGetSymbolAddress((void**)&h,     g_h);
    cudaGetSymbolAddress((void**)&h1,    g_h1);
    cudaGetSymbolAddress((void**)&hl,    g_hl);
    cudaGetSymbolAddress((void**)&z,     g_z);
    cudaGetSymbolAddress((void**)&d0,    g_d0);
    cudaGetSymbolAddress((void**)&y,     g_y);
    cudaGetSymbolAddress((void**)&cnt,   g_cnt);
    cudaGetSymbolAddress((void**)&gidx1, g_gidx1);
    cudaGetSymbolAddress((void**)&ginv1, g_ginv1);
    cudaGetSymbolAddress((void**)&gate1, g_gate1);
    cudaGetSymbolAddress((void**)&gidx2, g_gidx2);
    cudaGetSymbolAddress((void**)&lidx2, g_lidx2);
    cudaGetSymbolAddress((void**)&ginv2, g_ginv2);
    cudaGetSymbolAddress((void**)&linv2, g_linv2);
    cudaGetSymbolAddress((void**)&gate2, g_gate2);
    cudaGetSymbolAddress((void**)&edge1, g_edge1);
    cudaGetSymbolAddress((void**)&deg1,  g_deg1);
    cudaGetSymbolAddress((void**)&edge2, g_edge2);
    cudaGetSymbolAddress((void**)&deg2,  g_deg2);

    int2* edge0; int* deg0;
    cudaGetSymbolAddress((void**)&edge0, g_edge);
    cudaGetSymbolAddress((void**)&deg0,  g_deg);

    const long SXW = (long)N0 * 128;
    const long SH  = (long)N0 * 128;
    const long SH1 = (long)N1 * 96;
    const long SHL = (long)N2 * 64;
    const long SZ  = (long)N2 * LATENT;
    const long SD0 = (long)N2 * 64;

    // 0. sparsify A0
    build_ell<<<N0 / 8, 256>>>(A0);

    // 1. encoder GCN1 + fused pool1 score
    gemmT<64,128,0><<<dim3(2, N0/128, BATCH), 256>>>(x, (long)N0*FIN, W1, xw, SXW, nullptr, 0, nullptr);
    spmmT<128,2><<<dim3(N0/2, 1, BATCH), dim3(128, 2)>>>(edge0, 0, deg0, 0, xw, SXW, b1, h, SH, 1, p1, y);

    // 2. pool1 selection
    cudaMemsetAsync(cnt, 0, (long)BATCH * N0 * sizeof(int));
    rankk<<<dim3(N0/256, N0/1024, BATCH), 256>>>(y, N0, cnt);
    compactk<4><<<BATCH, 1024>>>(cnt, y, N0, N1, p1, 128, nullptr, 0,
                                 gidx1, gidx1, gate1, ginv1, nullptr, 0);
    build_sub<<<dim3(N1/8, BATCH), 256>>>(edge0, 0, deg0, 0, gidx1, N1, ginv1, N0,
                                          edge1, deg1, N1);

    // 3. encoder GCN2 + fused pool2 score
    gemmT<128,64,1><<<dim3(1, N1/128, BATCH), 256>>>(h, SH, W2, xw, SXW, gidx1, N1, gate1);
    spmmT<64,4><<<dim3(N1/4, 1, BATCH), dim3(64, 4)>>>(edge1, (long)N1*DEGMAX, deg1, N1,
                                                       xw, SXW, b2, h1, SH1, 1, p2, y);

    // 4. pool2 selection
    cudaMemsetAsync(cnt, 0, (long)BATCH * N0 * sizeof(int));
    rankk<<<dim3(N1/256, N1/1024, BATCH), 256>>>(y, N1, cnt);
    compactk<2><<<BATCH, 1024>>>(cnt, y, N1, N2, p2, 64, gidx1, N1,
                                 gidx2, lidx2, gate2, ginv2, linv2, N1);
    build_sub<<<dim3(N2/8, BATCH), 256>>>(edge1, (long)N1*DEGMAX, deg1, N1, lidx2, N2, linv2, N1,
                                          edge2, deg2, N2);

    // 5. latent GCN
    gemmT<64,64,1><<<dim3(1, N2/128, BATCH), 256>>>(h1, SH1, Wlat, xw, SXW, lidx2, N2, gate2);
    spmmT<64,4><<<dim3(N2/4, 1, BATCH), dim3(64, 4)>>>(edge2, (long)N2*DEGMAX, deg2, N2,
                                                       xw, SXW, blat, hl, SHL, 0, nullptr, nullptr);

    // 6. reparameterize
    reparam<<<(BATCH*N2*LATENT + 255)/256, 256>>>(eps, meanOut, lvOut);

    // 7. decoder GCN0 (level2)
    gemmT<32,64,0><<<dim3(1, N2/128, BATCH), 256>>>(z, SZ, Wd0, xw, SXW, nullptr, 0, nullptr);
    spmmT<64,4><<<dim3(N2/4, 1, BATCH), dim3(64, 4)>>>(edge2, (long)N2*DEGMAX, deg2, N2,
                                                       xw, SXW, bd0, d0, SD0, 1, nullptr, nullptr);

    // 8. unpool->level1, decoder GCN1
    gemmT<64,96,2><<<dim3(2, N1/128, BATCH), 256>>>(d0, SD0, Wd1, xw, SXW, linv2, N1, nullptr);
    spmmT<96,2><<<dim3(N1/2, 1, BATCH), dim3(96, 2)>>>(edge1, (long)N1*DEGMAX, deg1, N1,
                                                       xw, SXW, bd1, h1, SH1, 1, nullptr, nullptr);

    // 9. unpool->level0, decoder GCN2
    gemmT<96,128,2><<<dim3(2, N0/128, BATCH), 256>>>(h1, SH1, Wd2, xw, SXW, ginv1, N0, nullptr);
    spmmT<128,2><<<dim3(N0/2, 1, BATCH), dim3(128, 2)>>>(edge0, 0, deg0, 0,
                                                         xw, SXW, bd2, h, SH, 1, nullptr, nullptr);

    // 10. output GCN + softplus
    gemmT<128,64,0><<<dim3(1, N0/128, BATCH), 256>>>(h, SH, Wout, xw, SXW, nullptr, 0, nullptr);
    spmmT<64,4><<<dim3(N0/4, 1, BATCH), dim3(64, 4)>>>(edge0, 0, deg0, 0,
                                                       xw, SXW, bout, out, (long)N0*FIN, 2, nullptr, nullptr);
}

// round 3
// speedup vs baseline: 3.5012x; 1.2534x over previous
#include <cuda_runtime.h>
#include <math.h>

#define BATCH  8
#define N0     4096
#define N1     2048
#define N2     1024
#define FIN    64
#define LATENT 32
#define DEGMAX 128

// ---------------- device scratch ----------------
__device__ int   g_deg[N0];
__device__ int2  g_edge[N0 * DEGMAX];

__device__ int   g_deg1[BATCH * N1];
__device__ int2  g_edge1[BATCH * N1 * DEGMAX];
__device__ int   g_deg2[BATCH * N2];
__device__ int2  g_edge2[BATCH * N2 * DEGMAX];
__device__ int   g_deg01[BATCH * N0];               // level0 rows, level1 cols (masked)
__device__ int2  g_edge01[BATCH * N0 * DEGMAX];

__device__ float g_xw[BATCH][N0 * 128];
__device__ float g_h [BATCH][N0 * 128];
__device__ float g_h1[BATCH][N1 * 96];
__device__ float g_hl[BATCH][N2 * 64];
__device__ float g_z [BATCH][N2 * LATENT];
__device__ float g_d0[BATCH][N2 * 64];
__device__ float g_y [BATCH][N0];

__device__ int   g_gidx1[BATCH][N1];
__device__ int   g_ginv1[BATCH][N0];
__device__ float g_gate1[BATCH][N1];
__device__ int   g_gidx2[BATCH][N2];
__device__ int   g_lidx2[BATCH][N2];
__device__ int   g_ginv2[BATCH][N0];
__device__ int   g_linv2[BATCH][N1];
__device__ float g_gate2[BATCH][N2];

// ---------------- ELL build ----------------
__global__ void build_ell(const float* __restrict__ A0)
{
    int row  = blockIdx.x * (blockDim.x >> 5) + (threadIdx.x >> 5);
    int lane = threadIdx.x & 31;
    if (row >= N0) return;
    const float* arow = A0 + (long)row * N0;
    int base = 0;
    for (int c0 = 0; c0 < N0; c0 += 32) {
        float v = arow[c0 + lane];
        unsigned m = __ballot_sync(0xffffffffu, v != 0.0f);
        if (v != 0.0f) {
            int pos = base + __popc(m & ((1u << lane) - 1u));
            if (pos < DEGMAX) {
                int2 e; e.x = c0 + lane; e.y = __float_as_int(v);
                g_edge[(long)row * DEGMAX + pos] = e;
            }
        }
        base += __popc(m);
    }
    if (lane == 0) g_deg[row] = base < DEGMAX ? base : DEGMAX;
}

// ------- sub-ELL build: rows optionally gathered (rowMapB) or identity, cols remapped ----
__global__ void build_sub(const int2* __restrict__ srcEdge, long seStride,
                          const int* __restrict__ srcDeg, long sdStride,
                          const int* __restrict__ rowMapB, long sMap,
                          const int* __restrict__ invB, long sInv,
                          int2* __restrict__ dstEdge, int* __restrict__ dstDeg,
                          int nrows)
{
    int b = blockIdx.y;
    int r = blockIdx.x * (blockDim.x >> 5) + (threadIdx.x >> 5);
    int lane = threadIdx.x & 31;
    if (r >= nrows) return;
    int src = rowMapB ? rowMapB[(long)b * sMap + r] : r;
    const int2* ep = srcEdge + (long)b * seStride + (long)src * DEGMAX;
    int deg = srcDeg[(long)b * sdStride + src];
    const int* inv = invB + (long)b * sInv;
    int2* op = dstEdge + ((long)b * nrows + r) * DEGMAX;
    int base = 0;
    for (int c0 = 0; c0 < deg; c0 += 32) {
        int e = c0 + lane;
        int mc = -1; int2 pk;
        if (e < deg) { pk = __ldg(ep + e); mc = __ldg(inv + pk.x); }
        unsigned m = __ballot_sync(0xffffffffu, mc >= 0);
        if (mc >= 0) {
            int pos = base + __popc(m & ((1u << lane) - 1u));
            int2 o; o.x = mc; o.y = pk.y;
            op[pos] = o;
        }
        base += __popc(m);
    }
    if (lane == 0) dstDeg[(long)b * nrows + r] = base;
}

// ---------------- GEMM: 128x64 tile, 8x4 per thread ----------------
// MODE 0: plain rows   MODE 1: gather rows * scale   MODE 2: inv rows (-1 -> zero)
// EPI: bit0 = bias + relu before store; bit1 = fused y += relu_row . p (atomicAdd)
template<int K, int C, int MODE, int EPI>
__global__ __launch_bounds__(256)
void gemmT(const float* __restrict__ Ab, long sA,
           const float* __restrict__ W,
           const float* __restrict__ bias,
           float* __restrict__ Ob, long sO,
           const int* __restrict__ mapB, long sMap,
           const float* __restrict__ scaleB,
           const float* __restrict__ p, float* __restrict__ yB)
{
    __shared__ float As[32][128];
    __shared__ float Ws[32][64];

    int b = blockIdx.z;
    const float* A = Ab + (long)b * sA;
    float*       O = Ob + (long)b * sO;
    int tid = threadIdx.x;
    int rowTile = blockIdx.y * 128;
    int colTile = blockIdx.x * 64;

    int lr = tid >> 1;
    int lk = (tid & 1) * 16;
    int grow = rowTile + lr;
    const float* asrc;
    float ascale = 1.0f;
    if (MODE == 0) {
        asrc = A + (long)grow * K;
    } else if (MODE == 1) {
        int s = mapB[(long)b * sMap + grow];
        asrc = A + (long)s * K;
        ascale = scaleB[(long)b * sMap + grow];
    } else {
        int s = mapB[(long)b * sMap + grow];
        asrc = (s >= 0) ? (A + (long)s * K) : nullptr;
    }

    int wr  = tid >> 3;
    int wc0 = (tid & 7) * 8;

    int ry = tid >> 4, rx = tid & 15;
    float acc[8][4];
#pragma unroll
    for (int i = 0; i < 8; i++)
#pragma unroll
        for (int j = 0; j < 4; j++) acc[i][j] = 0.0f;

    for (int kt = 0; kt < K; kt += 32) {
#pragma unroll
        for (int t = 0; t < 16; t += 4) {
            float4 v = asrc ? *(const float4*)(asrc + kt + lk + t)
                            : make_float4(0.f, 0.f, 0.f, 0.f);
            As[lk + t + 0][lr] = v.x * ascale;
            As[lk + t + 1][lr] = v.y * ascale;
            As[lk + t + 2][lr] = v.z * ascale;
            As[lk + t + 3][lr] = v.w * ascale;
        }
#pragma unroll
        for (int t = 0; t < 8; t += 4) {
            int cc = colTile + wc0 + t;
            float4 v = (cc < C) ? *(const float4*)(W + (long)(kt + wr) * C + cc)
                                : make_float4(0.f, 0.f, 0.f, 0.f);
            *(float4*)&Ws[wr][wc0 + t] = v;
        }
        __syncthreads();

#pragma unroll
        for (int kk = 0; kk < 32; kk++) {
            float4 a0 = *(const float4*)(&As[kk][ry * 8]);
            float4 a1 = *(const float4*)(&As[kk][ry * 8 + 4]);
            float4 w  = *(const float4*)(&Ws[kk][rx * 4]);
            acc[0][0] += a0.x * w.x; acc[0][1] += a0.x * w.y; acc[0][2] += a0.x * w.z; acc[0][3] += a0.x * w.w;
            acc[1][0] += a0.y * w.x; acc[1][1] += a0.y * w.y; acc[1][2] += a0.y * w.z; acc[1][3] += a0.y * w.w;
            acc[2][0] += a0.z * w.x; acc[2][1] += a0.z * w.y; acc[2][2] += a0.z * w.z; acc[2][3] += a0.z * w.w;
            acc[3][0] += a0.w * w.x; acc[3][1] += a0.w * w.y; acc[3][2] += a0.w * w.z; acc[3][3] += a0.w * w.w;
            acc[4][0] += a1.x * w.x; acc[4][1] += a1.x * w.y; acc[4][2] += a1.x * w.z; acc[4][3] += a1.x * w.w;
            acc[5][0] += a1.y * w.x; acc[5][1] += a1.y * w.y; acc[5][2] += a1.y * w.z; acc[5][3] += a1.y * w.w;
            acc[6][0] += a1.z * w.x; acc[6][1] += a1.z * w.y; acc[6][2] += a1.z * w.z; acc[6][3] += a1.z * w.w;
            acc[7][0] += a1.w * w.x; acc[7][1] += a1.w * w.y; acc[7][2] += a1.w * w.z; acc[7][3] += a1.w * w.w;
        }
        __syncthreads();
    }

    int cc = colTile + rx * 4;
    if (cc < C) {
        if (EPI == 0) {
#pragma unroll
            for (int i = 0; i < 8; i++) {
                long r = rowTile + ry * 8 + i;
                *(float4*)(O + r * C + cc) =
                    make_float4(acc[i][0], acc[i][1], acc[i][2], acc[i][3]);
            }
        } else {
            float4 bv = *(const float4*)(bias + cc);
            float4 pv = make_float4(0.f, 0.f, 0.f, 0.f);
            if (EPI & 2) pv = *(const float4*)(p + cc);
            float part[8];
#pragma unroll
            for (int i = 0; i < 8; i++) {
                long r = rowTile + ry * 8 + i;
                float4 o;
                o.x = fmaxf(acc[i][0] + bv.x, 0.0f);
                o.y = fmaxf(acc[i][1] + bv.y, 0.0f);
                o.z = fmaxf(acc[i][2] + bv.z, 0.0f);
                o.w = fmaxf(acc[i][3] + bv.w, 0.0f);
                *(float4*)(O + r * C + cc) = o;
                part[i] = o.x * pv.x + o.y * pv.y + o.z * pv.z + o.w * pv.w;
            }
            if (EPI & 2) {
#pragma unroll
                for (int i = 0; i < 8; i++) {
                    float v = part[i];
#pragma unroll
                    for (int o = 8; o > 0; o >>= 1)
                        v += __shfl_down_sync(0xffffffffu, v, o, 16);
                    if ((tid & 15) == 0)
                        atomicAdd(&yB[(long)b * N0 + rowTile + ry * 8 + i], v);
                }
            }
        }
    }
}

// ---------------- SpMM (single-hop ELL) + optional fused pooling score --------
// act: 0 none, 1 relu, 2 softplus ; bias nullable
template<int C, int RPB>
__global__ void spmmT(const int2* __restrict__ edgeB, long eStride,
                      const int*  __restrict__ degB,  long dStride,
                      const float* __restrict__ Xb, long sX,
                      const float* __restrict__ bias,
                      float* __restrict__ Ob, long sO,
                      int act,
                      const float* __restrict__ p, float* __restrict__ yB)
{
    __shared__ float sp[C];
    __shared__ float sred[RPB][C / 32];

    int b = blockIdx.z;
    const float* X = Xb + (long)b * sX;
    float*       O = Ob + (long)b * sO;
    int tx = threadIdx.x, ty = threadIdx.y;
    int tid = ty * C + tx;
    int r = blockIdx.x * RPB + ty;

    if (p) {
        for (int t = tid; t < C; t += C * RPB) sp[t] = p[t];
        __syncthreads();
    }

    int deg = degB[(long)b * dStride + r];
    const int2* ep = edgeB + (long)b * eStride + (long)r * DEGMAX;
    float acc = 0.0f;
#pragma unroll 4
    for (int e = 0; e < deg; e++) {
        int2 pk = __ldg(ep + e);
        acc += __int_as_float(pk.y) * __ldg(X + (long)pk.x * C + tx);
    }
    if (bias) acc += bias[tx];
    if (act == 1)      acc = fmaxf(acc, 0.0f);
    else if (act == 2) acc = fmaxf(acc, 0.0f) + log1pf(expf(-fabsf(acc)));
    O[(long)r * C + tx] = acc;

    if (p) {
        float d = acc * sp[tx];
#pragma unroll
        for (int o = 16; o > 0; o >>= 1) d += __shfl_down_sync(0xffffffffu, d, o);
        if ((tx & 31) == 0) sred[ty][tx >> 5] = d;
        __syncthreads();
        if (tx == 0) {
            float s = 0.0f;
#pragma unroll
            for (int w = 0; w < C / 32; w++) s += sred[ty][w];
            yB[(long)b * N0 + r] = s;
        }
    }
}

// -------- descending crossing search over a histogram (warp 0, lanes 0..31) --------
__device__ __forceinline__ void crossing(const int* hist, int nbins, int kneed,
                                         int lane, int* sbin, int* sG)
{
    int per = nbins >> 5;
    int d0 = lane * per;
    int local = 0;
    for (int d = d0; d < d0 + per; d++) local += hist[nbins - 1 - d];
    int incl = local;
#pragma unroll
    for (int o = 1; o < 32; o <<= 1) {
        int v = __shfl_up_sync(0xffffffffu, incl, o);
        if (lane >= o) incl += v;
    }
    int excl = incl - local;
    if (excl < kneed && incl >= kneed) {
        int c = excl;
        for (int d = d0;; d++) {
            int hh = hist[nbins - 1 - d];
            if (c + hh >= kneed) { *sbin = nbins - 1 - d; *sG = c; break; }
            c += hh;
        }
    }
}

__device__ __forceinline__ int blockscan_excl(int v, int* ssum, int tid)
{
    ssum[tid] = v; __syncthreads();
    for (int o = 1; o < 1024; o <<= 1) {
        int t = (tid >= o) ? ssum[tid - o] : 0;
        __syncthreads();
        ssum[tid] += t;
        __syncthreads();
    }
    int r = ssum[tid] - v;
    __syncthreads();
    return r;
}

// -------- exact top-k via 3-level radix select + fused compaction --------
template<int IPT>
__global__ __launch_bounds__(1024)
void selectk_radix(const float* __restrict__ yB, int n, int k,
                   const float* __restrict__ p, int Cp,
                   const int* __restrict__ parentB, long sPar,
                   int* __restrict__ gidxB, int* __restrict__ lidxB,
                   float* __restrict__ gateB,
                   int* __restrict__ ginvB,
                   int* __restrict__ linvB, int linvLen)
{
    __shared__ unsigned su[4096];
    __shared__ int hist[2048];
    __shared__ int ssum[1024];
    __shared__ int s_bin, s_G;
    __shared__ float srn;

    int b = blockIdx.x, tid = threadIdx.x;
    const float* y = yB + (long)b * N0;

    if (tid == 0) {
        float s = 0.0f;
        for (int c = 0; c < Cp; c++) { float v = p[c]; s += v * v; }
        srn = rsqrtf(s);
    }
    for (int i = tid; i < n; i += 1024) {
        unsigned s = __float_as_uint(y[i]);
        su[i] = (s & 0x80000000u) ? ~s : (s | 0x80000000u);
    }

    // ---- level 1: top 11 bits ----
    for (int i = tid; i < 2048; i += 1024) hist[i] = 0;
    __syncthreads();
    for (int i = tid; i < n; i += 1024) atomicAdd(&hist[su[i] >> 21], 1);
    __syncthreads();
    if (tid < 32) crossing(hist, 2048, k, tid, &s_bin, &s_G);
    __syncthreads();
    unsigned b1 = (unsigned)s_bin;
    int need = k - s_G;
    __syncthreads();

    // ---- level 2: next 11 bits within bin b1 ----
    for (int i = tid; i < 2048; i += 1024) hist[i] = 0;
    __syncthreads();
    for (int i = tid; i < n; i += 1024)
        if ((su[i] >> 21) == b1) atomicAdd(&hist[(su[i] >> 10) & 0x7FFu], 1);
    __syncthreads();
    if (tid < 32) crossing(hist, 2048, need, tid, &s_bin, &s_G);
    __syncthreads();
    unsigned key2 = (b1 << 11) | (unsigned)s_bin;
    need -= s_G;
    __syncthreads();

    // ---- level 3: last 10 bits within key2 ----
    for (int i = tid; i < 1024; i += 1024) hist[i] = 0;
    __syncthreads();
    for (int i = tid; i < n; i += 1024)
        if ((su[i] >> 10) == key2) atomicAdd(&hist[su[i] & 0x3FFu], 1);
    __syncthreads();
    if (tid < 32) crossing(hist, 1024, need, tid, &s_bin, &s_G);
    __syncthreads();
    unsigned Tu = (key2 << 10) | (unsigned)s_bin;
    int E = need - s_G;          // # of ties (u == Tu) to keep, in index order
    __syncthreads();

    // ---- tie ranking + keep flags ----
    int i0 = tid * IPT;
    int eq[IPT], keep[IPT];
    int lsum = 0;
#pragma unroll
    for (int t = 0; t < IPT; t++) {
        unsigned u = su[i0 + t];
        eq[t] = (u == Tu);
        keep[t] = (u > Tu);
        lsum += eq[t];
    }
    int eqbase = blockscan_excl(lsum, ssum, tid);
    int run = eqbase;
#pragma unroll
    for (int t = 0; t < IPT; t++) {
        if (eq[t] && run < E) keep[t] = 1;
        run += eq[t];
    }

    // ---- compaction ----
    int ksum = 0;
#pragma unroll
    for (int t = 0; t < IPT; t++) ksum += keep[t];
    int base = blockscan_excl(ksum, ssum, tid);

    for (int i = tid; i < N0; i += 1024) ginvB[(long)b * N0 + i] = -1;
    if (linvB) for (int i = tid; i < linvLen; i += 1024) linvB[(long)b * linvLen + i] = -1;
    __syncthreads();

    float rn = srn;
    int pos = base;
#pragma unroll
    for (int t = 0; t < IPT; t++) {
        if (keep[t]) {
            int i = i0 + t;
            int g = parentB ? parentB[(long)b * sPar + i] : i;
            gidxB[(long)b * k + pos] = g;
            lidxB[(long)b * k + pos] = i;
            gateB[(long)b * k + pos] = tanhf(y[i] * rn);
            ginvB[(long)b * N0 + g] = pos;
            if (linvB) linvB[(long)b * linvLen + i] = pos;
            pos++;
        }
    }
}

// ---------------- reparameterization ----------------
__global__ void reparam(const float* __restrict__ eps,
                        float* __restrict__ meanOut, float* __restrict__ lvOut)
{
    int idx = blockIdx.x * blockDim.x + threadIdx.x;
    if (idx >= BATCH * N2 * LATENT) return;
    int b  = idx / (N2 * LATENT);
    int rc = idx % (N2 * LATENT);
    int r = rc / LATENT, c = rc % LATENT;
    float m  = g_hl[b][r * 64 + c];
    float lv = g_hl[b][r * 64 + 32 + c];
    meanOut[idx] = m;
    lvOut[idx]   = lv;
    g_z[b][rc]   = m + expf(0.5f * lv) * eps[idx];
}

// ---------------- launch ----------------
extern "C" void kernel_launch(void* const* d_in, const int* in_sizes, int n_in,
                              void* d_out, int out_size)
{
    const float* x    = (const float*)d_in[0];
    const float* eps  = (const float*)d_in[1];
    const float* A0   = (const float*)d_in[2];
    const float* W1   = (const float*)d_in[3];
    const float* b1   = (const float*)d_in[4];
    const float* p1   = (const float*)d_in[5];
    const float* W2   = (const float*)d_in[6];
    const float* b2   = (const float*)d_in[7];
    const float* p2   = (const float*)d_in[8];
    const float* Wlat = (const float*)d_in[9];
    const float* blat = (const float*)d_in[10];
    const float* Wd0  = (const float*)d_in[11];
    const float* bd0  = (const float*)d_in[12];
    const float* Wd1  = (const float*)d_in[13];
    const float* bd1  = (const float*)d_in[14];
    const float* Wd2  = (const float*)d_in[15];
    const float* bd2  = (const float*)d_in[16];
    const float* Wout = (const float*)d_in[17];
    const float* bout = (const float*)d_in[18];

    float* out     = (float*)d_out;
    float* meanOut = out + (long)BATCH * N0 * FIN;
    float* lvOut   = meanOut + (long)BATCH * N2 * LATENT;

    float *xw, *h, *h1, *hl, *z, *d0, *y, *gate1, *gate2;
    int *gidx1, *ginv1, *gidx2, *lidx2, *ginv2, *linv2;
    int2 *edge0, *edge1, *edge2, *edge01;
    int *deg0, *deg1, *deg2, *deg01;
    cudaGetSymbolAddress((void**)&xw,    g_xw);
    cudaGetSymbolAddress((void**)&h,     g_h);
    cudaGetSymbolAddress((void**)&h1,    g_h1);
    cudaGetSymbolAddress((void**)&hl,    g_hl);
    cudaGetSymbolAddress((void**)&z,     g_z);
    cudaGetSymbolAddress((void**)&d0,    g_d0);
    cudaGetSymbolAddress((void**)&y,     g_y);
    cudaGetSymbolAddress((void**)&gidx1, g_gidx1);
    cudaGetSymbolAddress((void**)&ginv1, g_ginv1);
    cudaGetSymbolAddress((void**)&gate1, g_gate1);
    cudaGetSymbolAddress((void**)&gidx2, g_gidx2);
    cudaGetSymbolAddress((void**)&lidx2, g_lidx2);
    cudaGetSymbolAddress((void**)&ginv2, g_ginv2);
    cudaGetSymbolAddress((void**)&linv2, g_linv2);
    cudaGetSymbolAddress((void**)&gate2, g_gate2);
    cudaGetSymbolAddress((void**)&edge0, g_edge);
    cudaGetSymbolAddress((void**)&deg0,  g_deg);
    cudaGetSymbolAddress((void**)&edge1, g_edge1);
    cudaGetSymbolAddress((void**)&deg1,  g_deg1);
    cudaGetSymbolAddress((void**)&edge2, g_edge2);
    cudaGetSymbolAddress((void**)&deg2,  g_deg2);
    cudaGetSymbolAddress((void**)&edge01, g_edge01);
    cudaGetSymbolAddress((void**)&deg01,  g_deg01);

    const long SXW = (long)N0 * 128;
    const long SH  = (long)N0 * 128;
    const long SH1 = (long)N1 * 96;
    const long SHL = (long)N2 * 64;
    const long SZ  = (long)N2 * LATENT;
    const long SD0 = (long)N2 * 64;

    // 0. sparsify A0
    build_ell<<<N0 / 8, 256>>>(A0);

    // 1. encoder GCN1 swapped: t = A0@x (C=64), h = relu(t@W1 + b1), fused y = h.p1
    spmmT<64,4><<<dim3(N0/4, 1, BATCH), dim3(64, 4)>>>(edge0, 0, deg0, 0,
                                                       x, (long)N0*FIN, nullptr, xw, SXW, 0, nullptr, nullptr);
    cudaMemsetAsync(y, 0, (long)BATCH * N0 * sizeof(float));
    gemmT<64,128,0,3><<<dim3(2, N0/128, BATCH), 256>>>(xw, SXW, W1, b1, h, SH,
                                                       nullptr, 0, nullptr, p1, y);

    // 2. pool1 selection (exact radix top-k + compaction), sub-adjacency builds
    selectk_radix<4><<<BATCH, 1024>>>(y, N0, N1, p1, 128, nullptr, 0,
                                      gidx1, gidx1, gate1, ginv1, nullptr, 0);
    build_sub<<<dim3(N1/8, BATCH), 256>>>(edge0, 0, deg0, 0, gidx1, N1, ginv1, N0,
                                          edge1, deg1, N1);
    build_sub<<<dim3(N0/8, BATCH), 256>>>(edge0, 0, deg0, 0, nullptr, 0, ginv1, N0,
                                          edge01, deg01, N0);

    // 3. encoder GCN2 + fused pool2 score
    gemmT<128,64,1,0><<<dim3(1, N1/128, BATCH), 256>>>(h, SH, W2, nullptr, xw, SXW,
                                                       gidx1, N1, gate1, nullptr, nullptr);
    spmmT<64,4><<<dim3(N1/4, 1, BATCH), dim3(64, 4)>>>(edge1, (long)N1*DEGMAX, deg1, N1,
                                                       xw, SXW, b2, h1, SH1, 1, p2, y);

    // 4. pool2 selection
    selectk_radix<2><<<BATCH, 1024>>>(y, N1, N2, p2, 64, gidx1, N1,
                                      gidx2, lidx2, gate2, ginv2, linv2, N1);
    build_sub<<<dim3(N2/8, BATCH), 256>>>(edge1, (long)N1*DEGMAX, deg1, N1, lidx2, N2, linv2, N1,
                                          edge2, deg2, N2);

    // 5. latent GCN
    gemmT<64,64,1,0><<<dim3(1, N2/128, BATCH), 256>>>(h1, SH1, Wlat, nullptr, xw, SXW,
                                                      lidx2, N2, gate2, nullptr, nullptr);
    spmmT<64,4><<<dim3(N2/4, 1, BATCH), dim3(64, 4)>>>(edge2, (long)N2*DEGMAX, deg2, N2,
                                                       xw, SXW, blat, hl, SHL, 0, nullptr, nullptr);

    // 6. reparameterize
    reparam<<<(BATCH*N2*LATENT + 255)/256, 256>>>(eps, meanOut, lvOut);

    // 7. decoder GCN0 (level2)
    gemmT<32,64,0,0><<<dim3(1, N2/128, BATCH), 256>>>(z, SZ, Wd0, nullptr, xw, SXW,
                                                      nullptr, 0, nullptr, nullptr, nullptr);
    spmmT<64,4><<<dim3(N2/4, 1, BATCH), dim3(64, 4)>>>(edge2, (long)N2*DEGMAX, deg2, N2,
                                                       xw, SXW, bd0, d0, SD0, 1, nullptr, nullptr);

    // 8. unpool->level1, decoder GCN1
    gemmT<64,96,2,0><<<dim3(2, N1/128, BATCH), 256>>>(d0, SD0, Wd1, nullptr, xw, SXW,
                                                      linv2, N1, nullptr, nullptr, nullptr);
    spmmT<96,2><<<dim3(N1/2, 1, BATCH), dim3(96, 2)>>>(edge1, (long)N1*DEGMAX, deg1, N1,
                                                       xw, SXW, bd1, h1, SH1, 1, nullptr, nullptr);

    // 9. decoder GCN2 swapped: t = A0@unpool(h1) via masked ELL (C=96), h = relu(t@Wd2 + bd2)
    spmmT<96,2><<<dim3(N0/2, 1, BATCH), dim3(96, 2)>>>(edge01, (long)N0*DEGMAX, deg01, N0,
                                                       h1, SH1, nullptr, xw, SXW, 0, nullptr, nullptr);
    gemmT<96,128,0,1><<<dim3(2, N0/128, BATCH), 256>>>(xw, SXW, Wd2, bd2, h, SH,
                                                       nullptr, 0, nullptr, nullptr, nullptr);

    // 10. output GCN + softplus
    gemmT<128,64,0,0><<<dim3(1, N0/128, BATCH), 256>>>(h, SH, Wout, nullptr, xw, SXW,
                                                       nullptr, 0, nullptr, nullptr, nullptr);
    spmmT<64,4><<<dim3(N0/4, 1, BATCH), dim3(64, 4)>>>(edge0, 0, deg0, 0,
                                                       xw, SXW, bout, out, (long)N0*FIN, 2, nullptr, nullptr);
}

// round 4
// speedup vs baseline: 3.5925x; 1.0261x over previous
#include <cuda_runtime.h>
#include <math.h>

#define BATCH  8
#define N0     4096
#define N1     2048
#define N2     1024
#define FIN    64
#define LATENT 32
#define DEGMAX 128

// ---- packed fp32x2 helpers (Blackwell FFMA2 — only reachable via PTX) ----
#define PACK2(out, v) \
    asm("mov.b64 %0, {%1, %1};" : "=l"(out) : "r"(__float_as_uint(v)))
#define FMA2(acc, a, b) \
    asm("fma.rn.f32x2 %0, %1, %2, %0;" : "+l"(acc) : "l"(a), "l"(b))
#define UNPACK2(lo, hi, in) \
    asm("mov.b64 {%0, %1}, %2;" : "=r"(lo), "=r"(hi) : "l"(in))

// ---------------- device scratch ----------------
__device__ int   g_deg[N0];
__device__ int2  g_edge[N0 * DEGMAX];

__device__ int   g_deg1[BATCH * N1];
__device__ int2  g_edge1[BATCH * N1 * DEGMAX];
__device__ int   g_deg2[BATCH * N2];
__device__ int2  g_edge2[BATCH * N2 * DEGMAX];
__device__ int   g_deg01[BATCH * N0];
__device__ int2  g_edge01[BATCH * N0 * DEGMAX];

__device__ float g_xw[BATCH][N0 * 128];
__device__ float g_h [BATCH][N0 * 128];
__device__ float g_h1[BATCH][N1 * 96];
__device__ float g_hl[BATCH][N2 * 64];
__device__ float g_z [BATCH][N2 * LATENT];
__device__ float g_d0[BATCH][N2 * 64];
__device__ float g_y [BATCH][N0];

__device__ int   g_gidx1[BATCH][N1];
__device__ int   g_ginv1[BATCH][N0];
__device__ float g_gate1[BATCH][N1];
__device__ int   g_gidx2[BATCH][N2];
__device__ int   g_lidx2[BATCH][N2];
__device__ int   g_ginv2[BATCH][N0];
__device__ int   g_linv2[BATCH][N1];
__device__ float g_gate2[BATCH][N2];

// ---------------- ELL build ----------------
__global__ void build_ell(const float* __restrict__ A0)
{
    int row  = blockIdx.x * (blockDim.x >> 5) + (threadIdx.x >> 5);
    int lane = threadIdx.x & 31;
    if (row >= N0) return;
    const float* arow = A0 + (long)row * N0;
    int base = 0;
    for (int c0 = 0; c0 < N0; c0 += 32) {
        float v = arow[c0 + lane];
        unsigned m = __ballot_sync(0xffffffffu, v != 0.0f);
        if (v != 0.0f) {
            int pos = base + __popc(m & ((1u << lane) - 1u));
            if (pos < DEGMAX) {
                int2 e; e.x = c0 + lane; e.y = __float_as_int(v);
                g_edge[(long)row * DEGMAX + pos] = e;
            }
        }
        base += __popc(m);
    }
    if (lane == 0) g_deg[row] = base < DEGMAX ? base : DEGMAX;
}

// ------- sub-ELL build ----------
__global__ void build_sub(const int2* __restrict__ srcEdge, long seStride,
                          const int* __restrict__ srcDeg, long sdStride,
                          const int* __restrict__ rowMapB, long sMap,
                          const int* __restrict__ invB, long sInv,
                          int2* __restrict__ dstEdge, int* __restrict__ dstDeg,
                          int nrows)
{
    int b = blockIdx.y;
    int r = blockIdx.x * (blockDim.x >> 5) + (threadIdx.x >> 5);
    int lane = threadIdx.x & 31;
    if (r >= nrows) return;
    int src = rowMapB ? rowMapB[(long)b * sMap + r] : r;
    const int2* ep = srcEdge + (long)b * seStride + (long)src * DEGMAX;
    int deg = srcDeg[(long)b * sdStride + src];
    const int* inv = invB + (long)b * sInv;
    int2* op = dstEdge + ((long)b * nrows + r) * DEGMAX;
    int base = 0;
    for (int c0 = 0; c0 < deg; c0 += 32) {
        int e = c0 + lane;
        int mc = -1; int2 pk;
        if (e < deg) { pk = __ldg(ep + e); mc = __ldg(inv + pk.x); }
        unsigned m = __ballot_sync(0xffffffffu, mc >= 0);
        if (mc >= 0) {
            int pos = base + __popc(m & ((1u << lane) - 1u));
            int2 o; o.x = mc; o.y = pk.y;
            op[pos] = o;
        }
        base += __popc(m);
    }
    if (lane == 0) dstDeg[(long)b * nrows + r] = base;
}

// ---------------- GEMM: 128x64 tile, 8x4 per thread, FFMA2 inner loop -------
// MODE 0: plain rows   MODE 1: gather rows * scale   MODE 2: inv rows (-1 -> zero)
// EPI: bit0 = bias + relu before store; bit1 = fused y += relu_row . p (atomicAdd)
template<int K, int C, int MODE, int EPI>
__global__ __launch_bounds__(256)
void gemmT(const float* __restrict__ Ab, long sA,
           const float* __restrict__ W,
           const float* __restrict__ bias,
           float* __restrict__ Ob, long sO,
           const int* __restrict__ mapB, long sMap,
           const float* __restrict__ scaleB,
           const float* __restrict__ p, float* __restrict__ yB)
{
    __shared__ float As[32][128];
    __shared__ float Ws[32][64];

    int b = blockIdx.z;
    const float* A = Ab + (long)b * sA;
    float*       O = Ob + (long)b * sO;
    int tid = threadIdx.x;
    int rowTile = blockIdx.y * 128;
    int colTile = blockIdx.x * 64;

    int lr = tid >> 1;
    int lk = (tid & 1) * 16;
    int grow = rowTile + lr;
    const float* asrc;
    float ascale = 1.0f;
    if (MODE == 0) {
        asrc = A + (long)grow * K;
    } else if (MODE == 1) {
        int s = mapB[(long)b * sMap + grow];
        asrc = A + (long)s * K;
        ascale = scaleB[(long)b * sMap + grow];
    } else {
        int s = mapB[(long)b * sMap + grow];
        asrc = (s >= 0) ? (A + (long)s * K) : nullptr;
    }

    int wr  = tid >> 3;
    int wc0 = (tid & 7) * 8;

    int ry = tid >> 4, rx = tid & 15;

    // packed accumulators: accP[rowpair][col] holds rows (2p, 2p+1) of col j
    unsigned long long accP[4][4];
#pragma unroll
    for (int i = 0; i < 4; i++)
#pragma unroll
        for (int j = 0; j < 4; j++) accP[i][j] = 0ull;

    for (int kt = 0; kt < K; kt += 32) {
#pragma unroll
        for (int t = 0; t < 16; t += 4) {
            float4 v = asrc ? *(const float4*)(asrc + kt + lk + t)
                            : make_float4(0.f, 0.f, 0.f, 0.f);
            As[lk + t + 0][lr] = v.x * ascale;
            As[lk + t + 1][lr] = v.y * ascale;
            As[lk + t + 2][lr] = v.z * ascale;
            As[lk + t + 3][lr] = v.w * ascale;
        }
#pragma unroll
        for (int t = 0; t < 8; t += 4) {
            int cc = colTile + wc0 + t;
            float4 v = (cc < C) ? *(const float4*)(W + (long)(kt + wr) * C + cc)
                                : make_float4(0.f, 0.f, 0.f, 0.f);
            *(float4*)&Ws[wr][wc0 + t] = v;
        }
        __syncthreads();

#pragma unroll
        for (int kk = 0; kk < 32; kk++) {
            // 8 A-rows as 4 natural f32x2 pairs (2 x LDS.128)
            ulonglong2 a01 = *(const ulonglong2*)(&As[kk][ry * 8]);
            ulonglong2 a23 = *(const ulonglong2*)(&As[kk][ry * 8 + 4]);
            float4 wv = *(const float4*)(&Ws[kk][rx * 4]);
            unsigned long long w0, w1, w2, w3;
            PACK2(w0, wv.x); PACK2(w1, wv.y); PACK2(w2, wv.z); PACK2(w3, wv.w);

            FMA2(accP[0][0], a01.x, w0); FMA2(accP[0][1], a01.x, w1);
            FMA2(accP[0][2], a01.x, w2); FMA2(accP[0][3], a01.x, w3);
            FMA2(accP[1][0], a01.y, w0); FMA2(accP[1][1], a01.y, w1);
            FMA2(accP[1][2], a01.y, w2); FMA2(accP[1][3], a01.y, w3);
            FMA2(accP[2][0], a23.x, w0); FMA2(accP[2][1], a23.x, w1);
            FMA2(accP[2][2], a23.x, w2); FMA2(accP[2][3], a23.x, w3);
            FMA2(accP[3][0], a23.y, w0); FMA2(accP[3][1], a23.y, w1);
            FMA2(accP[3][2], a23.y, w2); FMA2(accP[3][3], a23.y, w3);
        }
        __syncthreads();
    }

    // unpack to scalar accumulators
    float acc[8][4];
#pragma unroll
    for (int i = 0; i < 4; i++)
#pragma unroll
        for (int j = 0; j < 4; j++) {
            unsigned lo, hi;
            UNPACK2(lo, hi, accP[i][j]);
            acc[2 * i][j]     = __uint_as_float(lo);
            acc[2 * i + 1][j] = __uint_as_float(hi);
        }

    int cc = colTile + rx * 4;
    if (cc < C) {
        if (EPI == 0) {
#pragma unroll
            for (int i = 0; i < 8; i++) {
                long r = rowTile + ry * 8 + i;
                *(float4*)(O + r * C + cc) =
                    make_float4(acc[i][0], acc[i][1], acc[i][2], acc[i][3]);
            }
        } else {
            float4 bv = *(const float4*)(bias + cc);
            float4 pv = make_float4(0.f, 0.f, 0.f, 0.f);
            if (EPI & 2) pv = *(const float4*)(p + cc);
            float part[8];
#pragma unroll
            for (int i = 0; i < 8; i++) {
                long r = rowTile + ry * 8 + i;
                float4 o;
                o.x = fmaxf(acc[i][0] + bv.x, 0.0f);
                o.y = fmaxf(acc[i][1] + bv.y, 0.0f);
                o.z = fmaxf(acc[i][2] + bv.z, 0.0f);
                o.w = fmaxf(acc[i][3] + bv.w, 0.0f);
                *(float4*)(O + r * C + cc) = o;
                part[i] = o.x * pv.x + o.y * pv.y + o.z * pv.z + o.w * pv.w;
            }
            if (EPI & 2) {
#pragma unroll
                for (int i = 0; i < 8; i++) {
                    float v = part[i];
#pragma unroll
                    for (int o = 8; o > 0; o >>= 1)
                        v += __shfl_down_sync(0xffffffffu, v, o, 16);
                    if ((tid & 15) == 0)
                        atomicAdd(&yB[(long)b * N0 + rowTile + ry * 8 + i], v);
                }
            }
        }
    }
}

// ---------------- SpMM (single-hop ELL) + optional fused pooling score --------
template<int C, int RPB>
__global__ void spmmT(const int2* __restrict__ edgeB, long eStride,
                      const int*  __restrict__ degB,  long dStride,
                      const float* __restrict__ Xb, long sX,
                      const float* __restrict__ bias,
                      float* __restrict__ Ob, long sO,
                      int act,
                      const float* __restrict__ p, float* __restrict__ yB)
{
    __shared__ float sp[C];
    __shared__ float sred[RPB][C / 32];

    int b = blockIdx.z;
    const float* X = Xb + (long)b * sX;
    float*       O = Ob + (long)b * sO;
    int tx = threadIdx.x, ty = threadIdx.y;
    int tid = ty * C + tx;
    int r = blockIdx.x * RPB + ty;

    if (p) {
        for (int t = tid; t < C; t += C * RPB) sp[t] = p[t];
        __syncthreads();
    }

    int deg = degB[(long)b * dStride + r];
    const int2* ep = edgeB + (long)b * eStride + (long)r * DEGMAX;
    float acc = 0.0f;
#pragma unroll 4
    for (int e = 0; e < deg; e++) {
        int2 pk = __ldg(ep + e);
        acc += __int_as_float(pk.y) * __ldg(X + (long)pk.x * C + tx);
    }
    if (bias) acc += bias[tx];
    if (act == 1)      acc = fmaxf(acc, 0.0f);
    else if (act == 2) acc = fmaxf(acc, 0.0f) + log1pf(expf(-fabsf(acc)));
    O[(long)r * C + tx] = acc;

    if (p) {
        float d = acc * sp[tx];
#pragma unroll
        for (int o = 16; o > 0; o >>= 1) d += __shfl_down_sync(0xffffffffu, d, o);
        if ((tx & 31) == 0) sred[ty][tx >> 5] = d;
        __syncthreads();
        if (tx == 0) {
            float s = 0.0f;
#pragma unroll
            for (int w = 0; w < C / 32; w++) s += sred[ty][w];
            yB[(long)b * N0 + r] = s;
        }
    }
}

// -------- descending crossing search over a histogram (warp 0) --------
__device__ __forceinline__ void crossing(const int* hist, int nbins, int kneed,
                                         int lane, int* sbin, int* sG)
{
    int per = nbins >> 5;
    int d0 = lane * per;
    int local = 0;
    for (int d = d0; d < d0 + per; d++) local += hist[nbins - 1 - d];
    int incl = local;
#pragma unroll
    for (int o = 1; o < 32; o <<= 1) {
        int v = __shfl_up_sync(0xffffffffu, incl, o);
        if (lane >= o) incl += v;
    }
    int excl = incl - local;
    if (excl < kneed && incl >= kneed) {
        int c = excl;
        for (int d = d0;; d++) {
            int hh = hist[nbins - 1 - d];
            if (c + hh >= kneed) { *sbin = nbins - 1 - d; *sG = c; break; }
            c += hh;
        }
    }
}

// -------- warp-shuffle block exclusive scan (1024 threads, 3 barriers) --------
__device__ __forceinline__ int blockscan_excl(int v, int* swarp, int tid)
{
    int lane = tid & 31, w = tid >> 5;
    int incl = v;
#pragma unroll
    for (int o = 1; o < 32; o <<= 1) {
        int t = __shfl_up_sync(0xffffffffu, incl, o);
        if (lane >= o) incl += t;
    }
    __syncthreads();                 // protect swarp across repeated calls
    if (lane == 31) swarp[w] = incl;
    __syncthreads();
    if (w == 0) {
        int s = swarp[lane];
#pragma unroll
        for (int o = 1; o < 32; o <<= 1) {
            int t = __shfl_up_sync(0xffffffffu, s, o);
            if (lane >= o) s += t;
        }
        swarp[lane] = s;
    }
    __syncthreads();
    int base = w ? swarp[w - 1] : 0;
    return base + incl - v;
}

// -------- exact top-k via 3-level radix select + fused compaction --------
template<int IPT>
__global__ __launch_bounds__(1024)
void selectk_radix(const float* __restrict__ yB, int n, int k,
                   const float* __restrict__ p, int Cp,
                   const int* __restrict__ parentB, long sPar,
                   int* __restrict__ gidxB, int* __restrict__ lidxB,
                   float* __restrict__ gateB,
                   int* __restrict__ ginvB,
                   int* __restrict__ linvB, int linvLen)
{
    __shared__ unsigned su[4096];
    __shared__ int hist[2048];
    __shared__ int swarp[32];
    __shared__ int s_bin, s_G;
    __shared__ float srn;

    int b = blockIdx.x, tid = threadIdx.x;
    const float* y = yB + (long)b * N0;

    if (tid < 32) {
        float s = 0.0f;
        for (int c = tid; c < Cp; c += 32) { float v = p[c]; s += v * v; }
#pragma unroll
        for (int o = 16; o > 0; o >>= 1) s += __shfl_down_sync(0xffffffffu, s, o);
        if (tid == 0) srn = rsqrtf(s);
    }
    for (int i = tid; i < n; i += 1024) {
        unsigned s = __float_as_uint(y[i]);
        su[i] = (s & 0x80000000u) ? ~s : (s | 0x80000000u);
    }

    // ---- level 1: top 11 bits ----
    for (int i = tid; i < 2048; i += 1024) hist[i] = 0;
    __syncthreads();
    for (int i = tid; i < n; i += 1024) atomicAdd(&hist[su[i] >> 21], 1);
    __syncthreads();
    if (tid < 32) crossing(hist, 2048, k, tid, &s_bin, &s_G);
    __syncthreads();
    unsigned b1 = (unsigned)s_bin;
    int need = k - s_G;
    __syncthreads();

    // ---- level 2: next 11 bits ----
    for (int i = tid; i < 2048; i += 1024) hist[i] = 0;
    __syncthreads();
    for (int i = tid; i < n; i += 1024)
        if ((su[i] >> 21) == b1) atomicAdd(&hist[(su[i] >> 10) & 0x7FFu], 1);
    __syncthreads();
    if (tid < 32) crossing(hist, 2048, need, tid, &s_bin, &s_G);
    __syncthreads();
    unsigned key2 = (b1 << 11) | (unsigned)s_bin;
    need -= s_G;
    __syncthreads();

    // ---- level 3: last 10 bits ----
    for (int i = tid; i < 1024; i += 1024) hist[i] = 0;
    __syncthreads();
    for (int i = tid; i < n; i += 1024)
        if ((su[i] >> 10) == key2) atomicAdd(&hist[su[i] & 0x3FFu], 1);
    __syncthreads();
    if (tid < 32) crossing(hist, 1024, need, tid, &s_bin, &s_G);
    __syncthreads();
    unsigned Tu = (key2 << 10) | (unsigned)s_bin;
    int E = need - s_G;
    __syncthreads();

    // ---- tie ranking + keep flags ----
    int i0 = tid * IPT;
    int eq[IPT], keep[IPT];
    int lsum = 0;
#pragma unroll
    for (int t = 0; t < IPT; t++) {
        unsigned u = su[i0 + t];
        eq[t] = (u == Tu);
        keep[t] = (u > Tu);
        lsum += eq[t];
    }
    int eqbase = blockscan_excl(lsum, swarp, tid);
    int run = eqbase;
#pragma unroll
    for (int t = 0; t < IPT; t++) {
        if (eq[t] && run < E) keep[t] = 1;
        run += eq[t];
    }

    // ---- compaction ----
    int ksum = 0;
#pragma unroll
    for (int t = 0; t < IPT; t++) ksum += keep[t];
    int base = blockscan_excl(ksum, swarp, tid);

    for (int i = tid; i < N0; i += 1024) ginvB[(long)b * N0 + i] = -1;
    if (linvB) for (int i = tid; i < linvLen; i += 1024) linvB[(long)b * linvLen + i] = -1;
    __syncthreads();

    float rn = srn;
    int pos = base;
#pragma unroll
    for (int t = 0; t < IPT; t++) {
        if (keep[t]) {
            int i = i0 + t;
            int g = parentB ? parentB[(long)b * sPar + i] : i;
            gidxB[(long)b * k + pos] = g;
            lidxB[(long)b * k + pos] = i;
            gateB[(long)b * k + pos] = tanhf(y[i] * rn);
            ginvB[(long)b * N0 + g] = pos;
            if (linvB) linvB[(long)b * linvLen + i] = pos;
            pos++;
        }
    }
}

// ---------------- reparameterization ----------------
__global__ void reparam(const float* __restrict__ eps,
                        float* __restrict__ meanOut, float* __restrict__ lvOut)
{
    int idx = blockIdx.x * blockDim.x + threadIdx.x;
    if (idx >= BATCH * N2 * LATENT) return;
    int b  = idx / (N2 * LATENT);
    int rc = idx % (N2 * LATENT);
    int r = rc / LATENT, c = rc % LATENT;
    float m  = g_hl[b][r * 64 + c];
    float lv = g_hl[b][r * 64 + 32 + c];
    meanOut[idx] = m;
    lvOut[idx]   = lv;
    g_z[b][rc]   = m + expf(0.5f * lv) * eps[idx];
}

// ---------------- launch ----------------
extern "C" void kernel_launch(void* const* d_in, const int* in_sizes, int n_in,
                              void* d_out, int out_size)
{
    const float* x    = (const float*)d_in[0];
    const float* eps  = (const float*)d_in[1];
    const float* A0   = (const float*)d_in[2];
    const float* W1   = (const float*)d_in[3];
    const float* b1   = (const float*)d_in[4];
    const float* p1   = (const float*)d_in[5];
    const float* W2   = (const float*)d_in[6];
    const float* b2   = (const float*)d_in[7];
    const float* p2   = (const float*)d_in[8];
    const float* Wlat = (const float*)d_in[9];
    const float* blat = (const float*)d_in[10];
    const float* Wd0  = (const float*)d_in[11];
    const float* bd0  = (const float*)d_in[12];
    const float* Wd1  = (const float*)d_in[13];
    const float* bd1  = (const float*)d_in[14];
    const float* Wd2  = (const float*)d_in[15];
    const float* bd2  = (const float*)d_in[16];
    const float* Wout = (const float*)d_in[17];
    const float* bout = (const float*)d_in[18];

    float* out     = (float*)d_out;
    float* meanOut = out + (long)BATCH * N0 * FIN;
    float* lvOut   = meanOut + (long)BATCH * N2 * LATENT;

    float *xw, *h, *h1, *hl, *z, *d0, *y, *gate1, *gate2;
    int *gidx1, *ginv1, *gidx2, *lidx2, *ginv2, *linv2;
    int2 *edge0, *edge1, *edge2, *edge01;
    int *deg0, *deg1, *deg2, *deg01;
    cudaGetSymbolAddress((void**)&xw,    g_xw);
    cudaGetSymbolAddress((void**)&h,     g_h);
    cudaGetSymbolAddress((void**)&h1,    g_h1);
    cudaGetSymbolAddress((void**)&hl,    g_hl);
    cudaGetSymbolAddress((void**)&z,     g_z);
    cudaGetSymbolAddress((void**)&d0,    g_d0);
    cudaGetSymbolAddress((void**)&y,     g_y);
    cudaGetSymbolAddress((void**)&gidx1, g_gidx1);
    cudaGetSymbolAddress((void**)&ginv1, g_ginv1);
    cudaGetSymbolAddress((void**)&gate1, g_gate1);
    cudaGetSymbolAddress((void**)&gidx2, g_gidx2);
    cudaGetSymbolAddress((void**)&lidx2, g_lidx2);
    cudaGetSymbolAddress((void**)&ginv2, g_ginv2);
    cudaGetSymbolAddress((void**)&linv2, g_linv2);
    cudaGetSymbolAddress((void**)&gate2, g_gate2);
    cudaGetSymbolAddress((void**)&edge0, g_edge);
    cudaGetSymbolAddress((void**)&deg0,  g_deg);
    cudaGetSymbolAddress((void**)&edge1, g_edge1);
    cudaGetSymbolAddress((void**)&deg1,  g_deg1);
    cudaGetSymbolAddress((void**)&edge2, g_edge2);
    cudaGetSymbolAddress((void**)&deg2,  g_deg2);
    cudaGetSymbolAddress((void**)&edge01, g_edge01);
    cudaGetSymbolAddress((void**)&deg01,  g_deg01);

    const long SXW = (long)N0 * 128;
    const long SH  = (long)N0 * 128;
    const long SH1 = (long)N1 * 96;
    const long SHL = (long)N2 * 64;
    const long SZ  = (long)N2 * LATENT;
    const long SD0 = (long)N2 * 64;

    // 0. sparsify A0
    build_ell<<<N0 / 8, 256>>>(A0);

    // 1. encoder GCN1 swapped: t = A0@x (C=64), h = relu(t@W1 + b1), fused y = h.p1
    spmmT<64,4><<<dim3(N0/4, 1, BATCH), dim3(64, 4)>>>(edge0, 0, deg0, 0,
                                                       x, (long)N0*FIN, nullptr, xw, SXW, 0, nullptr, nullptr);
    cudaMemsetAsync(y, 0, (long)BATCH * N0 * sizeof(float));
    gemmT<64,128,0,3><<<dim3(2, N0/128, BATCH), 256>>>(xw, SXW, W1, b1, h, SH,
                                                       nullptr, 0, nullptr, p1, y);

    // 2. pool1 selection, sub-adjacency builds
    selectk_radix<4><<<BATCH, 1024>>>(y, N0, N1, p1, 128, nullptr, 0,
                                      gidx1, gidx1, gate1, ginv1, nullptr, 0);
    build_sub<<<dim3(N1/8, BATCH), 256>>>(edge0, 0, deg0, 0, gidx1, N1, ginv1, N0,
                                          edge1, deg1, N1);
    build_sub<<<dim3(N0/8, BATCH), 256>>>(edge0, 0, deg0, 0, nullptr, 0, ginv1, N0,
                                          edge01, deg01, N0);

    // 3. encoder GCN2 + fused pool2 score
    gemmT<128,64,1,0><<<dim3(1, N1/128, BATCH), 256>>>(h, SH, W2, nullptr, xw, SXW,
                                                       gidx1, N1, gate1, nullptr, nullptr);
    spmmT<64,4><<<dim3(N1/4, 1, BATCH), dim3(64, 4)>>>(edge1, (long)N1*DEGMAX, deg1, N1,
                                                       xw, SXW, b2, h1, SH1, 1, p2, y);

    // 4. pool2 selection
    selectk_radix<2><<<BATCH, 1024>>>(y, N1, N2, p2, 64, gidx1, N1,
                                      gidx2, lidx2, gate2, ginv2, linv2, N1);
    build_sub<<<dim3(N2/8, BATCH), 256>>>(edge1, (long)N1*DEGMAX, deg1, N1, lidx2, N2, linv2, N1,
                                          edge2, deg2, N2);

    // 5. latent GCN
    gemmT<64,64,1,0><<<dim3(1, N2/128, BATCH), 256>>>(h1, SH1, Wlat, nullptr, xw, SXW,
                                                      lidx2, N2, gate2, nullptr, nullptr);
    spmmT<64,4><<<dim3(N2/4, 1, BATCH), dim3(64, 4)>>>(edge2, (long)N2*DEGMAX, deg2, N2,
                                                       xw, SXW, blat, hl, SHL, 0, nullptr, nullptr);

    // 6. reparameterize
    reparam<<<(BATCH*N2*LATENT + 255)/256, 256>>>(eps, meanOut, lvOut);

    // 7. decoder GCN0 (level2)
    gemmT<32,64,0,0><<<dim3(1, N2/128, BATCH), 256>>>(z, SZ, Wd0, nullptr, xw, SXW,
                                                      nullptr, 0, nullptr, nullptr, nullptr);
    spmmT<64,4><<<dim3(N2/4, 1, BATCH), dim3(64, 4)>>>(edge2, (long)N2*DEGMAX, deg2, N2,
                                                       xw, SXW, bd0, d0, SD0, 1, nullptr, nullptr);

    // 8. unpool->level1, decoder GCN1
    gemmT<64,96,2,0><<<dim3(2, N1/128, BATCH), 256>>>(d0, SD0, Wd1, nullptr, xw, SXW,
                                                      linv2, N1, nullptr, nullptr, nullptr);
    spmmT<96,2><<<dim3(N1/2, 1, BATCH), dim3(96, 2)>>>(edge1, (long)N1*DEGMAX, deg1, N1,
                                                       xw, SXW, bd1, h1, SH1, 1, nullptr, nullptr);

    // 9. decoder GCN2 swapped: t = A0@unpool(h1) via masked ELL (C=96)
    spmmT<96,2><<<dim3(N0/2, 1, BATCH), dim3(96, 2)>>>(edge01, (long)N0*DEGMAX, deg01, N0,
                                                       h1, SH1, nullptr, xw, SXW, 0, nullptr, nullptr);
    gemmT<96,128,0,1><<<dim3(2, N0/128, BATCH), 256>>>(xw, SXW, Wd2, bd2, h, SH,
                                                       nullptr, 0, nullptr, nullptr, nullptr);

    // 10. output GCN + softplus
    gemmT<128,64,0,0><<<dim3(1, N0/128, BATCH), 256>>>(h, SH, Wout, nullptr, xw, SXW,
                                                       nullptr, 0, nullptr, nullptr, nullptr);
    spmmT<64,4><<<dim3(N0/4, 1, BATCH), dim3(64, 4)>>>(edge0, 0, deg0, 0,
                                                       xw, SXW, bout, out, (long)N0*FIN, 2, nullptr, nullptr);
}

// round 5
// speedup vs baseline: 3.7185x; 1.0351x over previous
#include <cuda_runtime.h>
#include <math.h>

#define BATCH  8
#define N0     4096
#define N1     2048
#define N2     1024
#define FIN    64
#define LATENT 32
#define DEGMAX 128

// ---- packed fp32x2 helpers (Blackwell FFMA2 — only reachable via PTX) ----
#define PACK2(out, v) \
    asm("mov.b64 %0, {%1, %1};" : "=l"(out) : "r"(__float_as_uint(v)))
#define FMA2(acc, a, b) \
    asm("fma.rn.f32x2 %0, %1, %2, %0;" : "+l"(acc) : "l"(a), "l"(b))
#define UNPACK2(lo, hi, in) \
    asm("mov.b64 {%0, %1}, %2;" : "=r"(lo), "=r"(hi) : "l"(in))

// ---------------- device scratch ----------------
__device__ int   g_deg[N0];
__device__ int2  g_edge[N0 * DEGMAX];

__device__ int   g_deg1[BATCH * N1];
__device__ int2  g_edge1[BATCH * N1 * DEGMAX];
__device__ int   g_deg2[BATCH * N2];
__device__ int2  g_edge2[BATCH * N2 * DEGMAX];
__device__ int   g_deg01[BATCH * N0];
__device__ int2  g_edge01[BATCH * N0 * DEGMAX];

__device__ float g_xw[BATCH][N0 * 128];
__device__ float g_h [BATCH][N0 * 128];
__device__ float g_h1[BATCH][N1 * 96];
__device__ float g_hl[BATCH][N2 * 64];
__device__ float g_d0[BATCH][N2 * 64];
__device__ float g_y [BATCH][N0];

__device__ int   g_gidx1[BATCH][N1];
__device__ int   g_ginv1[BATCH][N0];
__device__ float g_gate1[BATCH][N1];
__device__ int   g_gidx2[BATCH][N2];
__device__ int   g_lidx2[BATCH][N2];
__device__ int   g_ginv2[BATCH][N0];
__device__ int   g_linv2[BATCH][N1];
__device__ float g_gate2[BATCH][N2];

// ---- fused: dense A0 row -> smem ELL (+persist to g_edge) + spmm over x + y zero ----
__global__ __launch_bounds__(256)
void spmm0_build(const float* __restrict__ A0, const float* __restrict__ x,
                 float* __restrict__ xwB, float* __restrict__ yB)
{
    __shared__ int2 sedge[DEGMAX];
    __shared__ int scnt[8];
    __shared__ int soff[8];
    __shared__ int sdeg;

    int r = blockIdx.x;
    int tid = threadIdx.x, w = tid >> 5, lane = tid & 31;
    const float* arow = A0 + (long)r * N0;

    // phase A1: per-warp chunk counts (warp w owns cols [512w, 512w+512))
    int c0base = w * 512;
    int cnt = 0;
    for (int cc = c0base + lane; cc < c0base + 512; cc += 32) {
        unsigned m = __ballot_sync(0xffffffffu, arow[cc] != 0.0f);
        cnt += __popc(m);
    }
    if (lane == 0) scnt[w] = cnt;
    __syncthreads();
    if (tid == 0) {
        int s = 0;
        for (int i = 0; i < 8; i++) { soff[i] = s; s += scnt[i]; }
        sdeg = s < DEGMAX ? s : DEGMAX;
    }
    __syncthreads();

    // phase A2: compact into smem (re-read hits L1)
    int pos = soff[w];
    for (int cc = c0base + lane; cc < c0base + 512; cc += 32) {
        float v = arow[cc];
        unsigned m = __ballot_sync(0xffffffffu, v != 0.0f);
        if (v != 0.0f) {
            int p2 = pos + __popc(m & ((1u << lane) - 1u));
            if (p2 < DEGMAX) { int2 e; e.x = cc; e.y = __float_as_int(v); sedge[p2] = e; }
        }
        pos += __popc(m);
    }
    __syncthreads();

    int deg = sdeg;
    for (int e = tid; e < deg; e += 256) g_edge[(long)r * DEGMAX + e] = sedge[e];
    if (tid == 0) g_deg[r] = deg;
    if (tid < BATCH) yB[(long)tid * N0 + r] = 0.0f;

    // phase B: xw[b][r][c] = sum_e v * x[b][col][c], c in [0,64)
    int c = tid & 63, grp = tid >> 6;
    for (int b = grp; b < BATCH; b += 4) {
        const float* X = x + (long)b * N0 * FIN;
        float acc = 0.0f;
#pragma unroll 4
        for (int e = 0; e < deg; e++) {
            int2 pk = sedge[e];
            acc += __int_as_float(pk.y) * __ldg(X + (long)pk.x * FIN + c);
        }
        xwB[(long)b * ((long)N0 * 128) + (long)r * 64 + c] = acc;
    }
}

// ------- sub-ELL build ----------
__global__ void build_sub(const int2* __restrict__ srcEdge, long seStride,
                          const int* __restrict__ srcDeg, long sdStride,
                          const int* __restrict__ rowMapB, long sMap,
                          const int* __restrict__ invB, long sInv,
                          int2* __restrict__ dstEdge, int* __restrict__ dstDeg,
                          int nrows)
{
    int b = blockIdx.y;
    int r = blockIdx.x * (blockDim.x >> 5) + (threadIdx.x >> 5);
    int lane = threadIdx.x & 31;
    if (r >= nrows) return;
    int src = rowMapB ? rowMapB[(long)b * sMap + r] : r;
    const int2* ep = srcEdge + (long)b * seStride + (long)src * DEGMAX;
    int deg = srcDeg[(long)b * sdStride + src];
    const int* inv = invB + (long)b * sInv;
    int2* op = dstEdge + ((long)b * nrows + r) * DEGMAX;
    int base = 0;
    for (int c0 = 0; c0 < deg; c0 += 32) {
        int e = c0 + lane;
        int mc = -1; int2 pk;
        if (e < deg) { pk = __ldg(ep + e); mc = __ldg(inv + pk.x); }
        unsigned m = __ballot_sync(0xffffffffu, mc >= 0);
        if (mc >= 0) {
            int pos = base + __popc(m & ((1u << lane) - 1u));
            int2 o; o.x = mc; o.y = pk.y;
            op[pos] = o;
        }
        base += __popc(m);
    }
    if (lane == 0) dstDeg[(long)b * nrows + r] = base;
}

// ---------------- GEMM: 128x64 tile, 8x4 per thread, FFMA2 inner loop -------
// MODE 0: plain rows   MODE 1: gather rows * scale   MODE 2: inv rows (-1 -> zero)
// MODE 3: reparameterize rows: A = hl[r][0:32]=mean, [32:64]=logvar; z fed to GEMM,
//         mean/logvar emitted to outputs. (K must be 32; grid.x must be 1.)
// EPI: bit0 = bias + relu before store; bit1 = fused y += relu_row . p (atomicAdd)
template<int K, int C, int MODE, int EPI>
__global__ __launch_bounds__(256)
void gemmT(const float* __restrict__ Ab, long sA,
           const float* __restrict__ W,
           const float* __restrict__ bias,
           float* __restrict__ Ob, long sO,
           const int* __restrict__ mapB, long sMap,
           const float* __restrict__ scaleB,
           const float* __restrict__ p, float* __restrict__ yB,
           const float* __restrict__ epsB,
           float* __restrict__ meanOutB, float* __restrict__ lvOutB)
{
    __shared__ float As[32][128];
    __shared__ float Ws[32][64];

    int b = blockIdx.z;
    const float* A = Ab + (long)b * sA;
    float*       O = Ob + (long)b * sO;
    int tid = threadIdx.x;
    int rowTile = blockIdx.y * 128;
    int colTile = blockIdx.x * 64;

    int lr = tid >> 1;
    int lk = (tid & 1) * 16;
    int grow = rowTile + lr;
    const float* asrc = nullptr;
    float ascale = 1.0f;
    if (MODE == 0) {
        asrc = A + (long)grow * K;
    } else if (MODE == 1) {
        int s = mapB[(long)b * sMap + grow];
        asrc = A + (long)s * K;
        ascale = scaleB[(long)b * sMap + grow];
    } else if (MODE == 2) {
        int s = mapB[(long)b * sMap + grow];
        asrc = (s >= 0) ? (A + (long)s * K) : nullptr;
    }

    int wr  = tid >> 3;
    int wc0 = (tid & 7) * 8;

    int ry = tid >> 4, rx = tid & 15;

    unsigned long long accP[4][4];
#pragma unroll
    for (int i = 0; i < 4; i++)
#pragma unroll
        for (int j = 0; j < 4; j++) accP[i][j] = 0ull;

    for (int kt = 0; kt < K; kt += 32) {
        if (MODE == 3) {
            // K == 32, single k-tile: z = mean + exp(0.5*logvar)*eps
#pragma unroll
            for (int t = 0; t < 16; t += 4) {
                float4 m  = *(const float4*)(A + (long)grow * 64 + lk + t);
                float4 lv = *(const float4*)(A + (long)grow * 64 + 32 + lk + t);
                float4 e  = *(const float4*)(epsB + ((long)b * N2 + grow) * LATENT + lk + t);
                float4 z;
                z.x = m.x + expf(0.5f * lv.x) * e.x;
                z.y = m.y + expf(0.5f * lv.y) * e.y;
                z.z = m.z + expf(0.5f * lv.z) * e.z;
                z.w = m.w + expf(0.5f * lv.w) * e.w;
                As[lk + t + 0][lr] = z.x;
                As[lk + t + 1][lr] = z.y;
                As[lk + t + 2][lr] = z.z;
                As[lk + t + 3][lr] = z.w;
                *(float4*)(meanOutB + ((long)b * N2 + grow) * LATENT + lk + t) = m;
                *(float4*)(lvOutB   + ((long)b * N2 + grow) * LATENT + lk + t) = lv;
            }
        } else {
#pragma unroll
            for (int t = 0; t < 16; t += 4) {
                float4 v = asrc ? *(const float4*)(asrc + kt + lk + t)
                                : make_float4(0.f, 0.f, 0.f, 0.f);
                As[lk + t + 0][lr] = v.x * ascale;
                As[lk + t + 1][lr] = v.y * ascale;
                As[lk + t + 2][lr] = v.z * ascale;
                As[lk + t + 3][lr] = v.w * ascale;
            }
        }
#pragma unroll
        for (int t = 0; t < 8; t += 4) {
            int cc = colTile + wc0 + t;
            float4 v = (cc < C) ? *(const float4*)(W + (long)(kt + wr) * C + cc)
                                : make_float4(0.f, 0.f, 0.f, 0.f);
            *(float4*)&Ws[wr][wc0 + t] = v;
        }
        __syncthreads();

#pragma unroll
        for (int kk = 0; kk < 32; kk++) {
            ulonglong2 a01 = *(const ulonglong2*)(&As[kk][ry * 8]);
            ulonglong2 a23 = *(const ulonglong2*)(&As[kk][ry * 8 + 4]);
            float4 wv = *(const float4*)(&Ws[kk][rx * 4]);
            unsigned long long w0, w1, w2, w3;
            PACK2(w0, wv.x); PACK2(w1, wv.y); PACK2(w2, wv.z); PACK2(w3, wv.w);

            FMA2(accP[0][0], a01.x, w0); FMA2(accP[0][1], a01.x, w1);
            FMA2(accP[0][2], a01.x, w2); FMA2(accP[0][3], a01.x, w3);
            FMA2(accP[1][0], a01.y, w0); FMA2(accP[1][1], a01.y, w1);
            FMA2(accP[1][2], a01.y, w2); FMA2(accP[1][3], a01.y, w3);
            FMA2(accP[2][0], a23.x, w0); FMA2(accP[2][1], a23.x, w1);
            FMA2(accP[2][2], a23.x, w2); FMA2(accP[2][3], a23.x, w3);
            FMA2(accP[3][0], a23.y, w0); FMA2(accP[3][1], a23.y, w1);
            FMA2(accP[3][2], a23.y, w2); FMA2(accP[3][3], a23.y, w3);
        }
        __syncthreads();
    }

    float acc[8][4];
#pragma unroll
    for (int i = 0; i < 4; i++)
#pragma unroll
        for (int j = 0; j < 4; j++) {
            unsigned lo, hi;
            UNPACK2(lo, hi, accP[i][j]);
            acc[2 * i][j]     = __uint_as_float(lo);
            acc[2 * i + 1][j] = __uint_as_float(hi);
        }

    int cc = colTile + rx * 4;
    if (cc < C) {
        if (EPI == 0) {
#pragma unroll
            for (int i = 0; i < 8; i++) {
                long r = rowTile + ry * 8 + i;
                *(float4*)(O + r * C + cc) =
                    make_float4(acc[i][0], acc[i][1], acc[i][2], acc[i][3]);
            }
        } else {
            float4 bv = *(const float4*)(bias + cc);
            float4 pv = make_float4(0.f, 0.f, 0.f, 0.f);
            if (EPI & 2) pv = *(const float4*)(p + cc);
            float part[8];
#pragma unroll
            for (int i = 0; i < 8; i++) {
                long r = rowTile + ry * 8 + i;
                float4 o;
                o.x = fmaxf(acc[i][0] + bv.x, 0.0f);
                o.y = fmaxf(acc[i][1] + bv.y, 0.0f);
                o.z = fmaxf(acc[i][2] + bv.z, 0.0f);
                o.w = fmaxf(acc[i][3] + bv.w, 0.0f);
                *(float4*)(O + r * C + cc) = o;
                part[i] = o.x * pv.x + o.y * pv.y + o.z * pv.z + o.w * pv.w;
            }
            if (EPI & 2) {
#pragma unroll
                for (int i = 0; i < 8; i++) {
                    float v = part[i];
#pragma unroll
                    for (int o = 8; o > 0; o >>= 1)
                        v += __shfl_down_sync(0xffffffffu, v, o, 16);
                    if ((tid & 15) == 0)
                        atomicAdd(&yB[(long)b * N0 + rowTile + ry * 8 + i], v);
                }
            }
        }
    }
}

// ---------------- SpMM (single-hop ELL) + optional fused pooling score --------
template<int C, int RPB>
__global__ void spmmT(const int2* __restrict__ edgeB, long eStride,
                      const int*  __restrict__ degB,  long dStride,
                      const float* __restrict__ Xb, long sX,
                      const float* __restrict__ bias,
                      float* __restrict__ Ob, long sO,
                      int act,
                      const float* __restrict__ p, float* __restrict__ yB)
{
    __shared__ float sp[C];
    __shared__ float sred[RPB][C / 32];

    int b = blockIdx.z;
    const float* X = Xb + (long)b * sX;
    float*       O = Ob + (long)b * sO;
    int tx = threadIdx.x, ty = threadIdx.y;
    int tid = ty * C + tx;
    int r = blockIdx.x * RPB + ty;

    if (p) {
        for (int t = tid; t < C; t += C * RPB) sp[t] = p[t];
        __syncthreads();
    }

    int deg = degB[(long)b * dStride + r];
    const int2* ep = edgeB + (long)b * eStride + (long)r * DEGMAX;
    float acc = 0.0f;
#pragma unroll 4
    for (int e = 0; e < deg; e++) {
        int2 pk = __ldg(ep + e);
        acc += __int_as_float(pk.y) * __ldg(X + (long)pk.x * C + tx);
    }
    if (bias) acc += bias[tx];
    if (act == 1)      acc = fmaxf(acc, 0.0f);
    else if (act == 2) acc = fmaxf(acc, 0.0f) + log1pf(expf(-fabsf(acc)));
    O[(long)r * C + tx] = acc;

    if (p) {
        float d = acc * sp[tx];
#pragma unroll
        for (int o = 16; o > 0; o >>= 1) d += __shfl_down_sync(0xffffffffu, d, o);
        if ((tx & 31) == 0) sred[ty][tx >> 5] = d;
        __syncthreads();
        if (tx == 0) {
            float s = 0.0f;
#pragma unroll
            for (int w = 0; w < C / 32; w++) s += sred[ty][w];
            yB[(long)b * N0 + r] = s;
        }
    }
}

// -------- descending crossing search over a histogram (warp 0) --------
__device__ __forceinline__ void crossing(const int* hist, int nbins, int kneed,
                                         int lane, int* sbin, int* sG)
{
    int per = nbins >> 5;
    int d0 = lane * per;
    int local = 0;
    for (int d = d0; d < d0 + per; d++) local += hist[nbins - 1 - d];
    int incl = local;
#pragma unroll
    for (int o = 1; o < 32; o <<= 1) {
        int v = __shfl_up_sync(0xffffffffu, incl, o);
        if (lane >= o) incl += v;
    }
    int excl = incl - local;
    if (excl < kneed && incl >= kneed) {
        int c = excl;
        for (int d = d0;; d++) {
            int hh = hist[nbins - 1 - d];
            if (c + hh >= kneed) { *sbin = nbins - 1 - d; *sG = c; break; }
            c += hh;
        }
    }
}

// -------- warp-shuffle block exclusive scan (1024 threads) --------
__device__ __forceinline__ int blockscan_excl(int v, int* swarp, int tid)
{
    int lane = tid & 31, w = tid >> 5;
    int incl = v;
#pragma unroll
    for (int o = 1; o < 32; o <<= 1) {
        int t = __shfl_up_sync(0xffffffffu, incl, o);
        if (lane >= o) incl += t;
    }
    __syncthreads();
    if (lane == 31) swarp[w] = incl;
    __syncthreads();
    if (w == 0) {
        int s = swarp[lane];
#pragma unroll
        for (int o = 1; o < 32; o <<= 1) {
            int t = __shfl_up_sync(0xffffffffu, s, o);
            if (lane >= o) s += t;
        }
        swarp[lane] = s;
    }
    __syncthreads();
    int base = w ? swarp[w - 1] : 0;
    return base + incl - v;
}

// -------- exact top-k: one histogram pass + boundary-bin exact rank --------
template<int IPT>
__global__ __launch_bounds__(1024)
void selectk_fast(const float* __restrict__ yB, int n, int k,
                  const float* __restrict__ p, int Cp,
                  const int* __restrict__ parentB, long sPar,
                  int* __restrict__ gidxB, int* __restrict__ lidxB,
                  float* __restrict__ gateB,
                  int* __restrict__ ginvB,
                  int* __restrict__ linvB, int linvLen)
{
    __shared__ unsigned su[4096];
    __shared__ int hist[2048];
    __shared__ unsigned char skeep[4096];
    __shared__ int glist[4096];
    __shared__ int swarp[32];
    __shared__ int s_bin, s_G, s_cnt;
    __shared__ float srn;

    int b = blockIdx.x, tid = threadIdx.x;
    const float* y = yB + (long)b * N0;

    if (tid < 32) {
        float s = 0.0f;
        for (int c = tid; c < Cp; c += 32) { float v = p[c]; s += v * v; }
#pragma unroll
        for (int o = 16; o > 0; o >>= 1) s += __shfl_down_sync(0xffffffffu, s, o);
        if (tid == 0) { srn = rsqrtf(s); s_cnt = 0; }
    }
    for (int i = tid; i < n; i += 1024) {
        unsigned s = __float_as_uint(y[i]);
        su[i] = (s & 0x80000000u) ? ~s : (s | 0x80000000u);
    }
    for (int i = tid; i < 2048; i += 1024) hist[i] = 0;
    __syncthreads();
    for (int i = tid; i < n; i += 1024) atomicAdd(&hist[su[i] >> 21], 1);
    __syncthreads();
    if (tid < 32) crossing(hist, 2048, k, tid, &s_bin, &s_G);
    __syncthreads();
    unsigned b1 = (unsigned)s_bin;
    int need = k - s_G;

    // keep = strictly-above bins; gather boundary bin (expected ~n/2048 elems)
    for (int i = tid; i < n; i += 1024) {
        unsigned bin = su[i] >> 21;
        skeep[i] = (bin > b1);
        if (bin == b1) glist[atomicAdd(&s_cnt, 1)] = i;
    }
    __syncthreads();
    int cnt = s_cnt;
    // exact rank within boundary set: (key desc, index asc)
    for (int t = tid; t < cnt; t += 1024) {
        int i = glist[t];
        unsigned ui = su[i];
        int rk = 0;
        for (int j = 0; j < cnt; j++) {
            int jj = glist[j];
            unsigned uj = su[jj];
            rk += (uj > ui) || (uj == ui && jj < i);
        }
        if (rk < need) skeep[i] = 1;
    }
    __syncthreads();

    // compaction
    int i0 = tid * IPT;
    int keep[IPT];
    int ksum = 0;
#pragma unroll
    for (int t = 0; t < IPT; t++) { keep[t] = skeep[i0 + t]; ksum += keep[t]; }
    int base = blockscan_excl(ksum, swarp, tid);

    for (int i = tid; i < N0; i += 1024) ginvB[(long)b * N0 + i] = -1;
    if (linvB) for (int i = tid; i < linvLen; i += 1024) linvB[(long)b * linvLen + i] = -1;
    __syncthreads();

    float rn = srn;
    int pos = base;
#pragma unroll
    for (int t = 0; t < IPT; t++) {
        if (keep[t]) {
            int i = i0 + t;
            int g = parentB ? parentB[(long)b * sPar + i] : i;
            gidxB[(long)b * k + pos] = g;
            lidxB[(long)b * k + pos] = i;
            gateB[(long)b * k + pos] = tanhf(y[i] * rn);
            ginvB[(long)b * N0 + g] = pos;
            if (linvB) linvB[(long)b * linvLen + i] = pos;
            pos++;
        }
    }
}

// ---------------- launch ----------------
extern "C" void kernel_launch(void* const* d_in, const int* in_sizes, int n_in,
                              void* d_out, int out_size)
{
    const float* x    = (const float*)d_in[0];
    const float* eps  = (const float*)d_in[1];
    const float* A0   = (const float*)d_in[2];
    const float* W1   = (const float*)d_in[3];
    const float* b1   = (const float*)d_in[4];
    const float* p1   = (const float*)d_in[5];
    const float* W2   = (const float*)d_in[6];
    const float* b2   = (const float*)d_in[7];
    const float* p2   = (const float*)d_in[8];
    const float* Wlat = (const float*)d_in[9];
    const float* blat = (const float*)d_in[10];
    const float* Wd0  = (const float*)d_in[11];
    const float* bd0  = (const float*)d_in[12];
    const float* Wd1  = (const float*)d_in[13];
    const float* bd1  = (const float*)d_in[14];
    const float* Wd2  = (const float*)d_in[15];
    const float* bd2  = (const float*)d_in[16];
    const float* Wout = (const float*)d_in[17];
    const float* bout = (const float*)d_in[18];

    float* out     = (float*)d_out;
    float* meanOut = out + (long)BATCH * N0 * FIN;
    float* lvOut   = meanOut + (long)BATCH * N2 * LATENT;

    float *xw, *h, *h1, *hl, *d0, *y, *gate1, *gate2;
    int *gidx1, *ginv1, *gidx2, *lidx2, *ginv2, *linv2;
    int2 *edge0, *edge1, *edge2, *edge01;
    int *deg0, *deg1, *deg2, *deg01;
    cudaGetSymbolAddress((void**)&xw,    g_xw);
    cudaGetSymbolAddress((void**)&h,     g_h);
    cudaGetSymbolAddress((void**)&h1,    g_h1);
    cudaGetSymbolAddress((void**)&hl,    g_hl);
    cudaGetSymbolAddress((void**)&d0,    g_d0);
    cudaGetSymbolAddress((void**)&y,     g_y);
    cudaGetSymbolAddress((void**)&gidx1, g_gidx1);
    cudaGetSymbolAddress((void**)&ginv1, g_ginv1);
    cudaGetSymbolAddress((void**)&gate1, g_gate1);
    cudaGetSymbolAddress((void**)&gidx2, g_gidx2);
    cudaGetSymbolAddress((void**)&lidx2, g_lidx2);
    cudaGetSymbolAddress((void**)&ginv2, g_ginv2);
    cudaGetSymbolAddress((void**)&linv2, g_linv2);
    cudaGetSymbolAddress((void**)&gate2, g_gate2);
    cudaGetSymbolAddress((void**)&edge0, g_edge);
    cudaGetSymbolAddress((void**)&deg0,  g_deg);
    cudaGetSymbolAddress((void**)&edge1, g_edge1);
    cudaGetSymbolAddress((void**)&deg1,  g_deg1);
    cudaGetSymbolAddress((void**)&edge2, g_edge2);
    cudaGetSymbolAddress((void**)&deg2,  g_deg2);
    cudaGetSymbolAddress((void**)&edge01, g_edge01);
    cudaGetSymbolAddress((void**)&deg01,  g_deg01);

    const long SXW = (long)N0 * 128;
    const long SH  = (long)N0 * 128;
    const long SH1 = (long)N1 * 96;
    const long SHL = (long)N2 * 64;
    const long SD0 = (long)N2 * 64;

    // 1. fused: sparsify A0 + t = A0@x (C=64) + zero y
    spmm0_build<<<N0, 256>>>(A0, x, xw, y);
    // h = relu(t@W1 + b1), fused y = h.p1
    gemmT<64,128,0,3><<<dim3(2, N0/128, BATCH), 256>>>(xw, SXW, W1, b1, h, SH,
        nullptr, 0, nullptr, p1, y, nullptr, nullptr, nullptr);

    // 2. pool1 selection + sub-adjacency builds
    selectk_fast<4><<<BATCH, 1024>>>(y, N0, N1, p1, 128, nullptr, 0,
                                     gidx1, gidx1, gate1, ginv1, nullptr, 0);
    build_sub<<<dim3(N1/8, BATCH), 256>>>(edge0, 0, deg0, 0, gidx1, N1, ginv1, N0,
                                          edge1, deg1, N1);
    build_sub<<<dim3(N0/8, BATCH), 256>>>(edge0, 0, deg0, 0, nullptr, 0, ginv1, N0,
                                          edge01, deg01, N0);

    // 3. encoder GCN2 + fused pool2 score
    gemmT<128,64,1,0><<<dim3(1, N1/128, BATCH), 256>>>(h, SH, W2, nullptr, xw, SXW,
        gidx1, N1, gate1, nullptr, nullptr, nullptr, nullptr, nullptr);
    spmmT<64,4><<<dim3(N1/4, 1, BATCH), dim3(64, 4)>>>(edge1, (long)N1*DEGMAX, deg1, N1,
                                                       xw, SXW, b2, h1, SH1, 1, p2, y);

    // 4. pool2 selection
    selectk_fast<2><<<BATCH, 1024>>>(y, N1, N2, p2, 64, gidx1, N1,
                                     gidx2, lidx2, gate2, ginv2, linv2, N1);
    build_sub<<<dim3(N2/8, BATCH), 256>>>(edge1, (long)N1*DEGMAX, deg1, N1, lidx2, N2, linv2, N1,
                                          edge2, deg2, N2);

    // 5. latent GCN
    gemmT<64,64,1,0><<<dim3(1, N2/128, BATCH), 256>>>(h1, SH1, Wlat, nullptr, xw, SXW,
        lidx2, N2, gate2, nullptr, nullptr, nullptr, nullptr, nullptr);
    spmmT<64,4><<<dim3(N2/4, 1, BATCH), dim3(64, 4)>>>(edge2, (long)N2*DEGMAX, deg2, N2,
                                                       xw, SXW, blat, hl, SHL, 0, nullptr, nullptr);

    // 6+7. decoder GCN0 with fused reparameterization (z on the fly, mean/lv emitted)
    gemmT<32,64,3,0><<<dim3(1, N2/128, BATCH), 256>>>(hl, SHL, Wd0, nullptr, xw, SXW,
        nullptr, 0, nullptr, nullptr, nullptr, eps, meanOut, lvOut);
    spmmT<64,4><<<dim3(N2/4, 1, BATCH), dim3(64, 4)>>>(edge2, (long)N2*DEGMAX, deg2, N2,
                                                       xw, SXW, bd0, d0, SD0, 1, nullptr, nullptr);

    // 8. unpool->level1, decoder GCN1
    gemmT<64,96,2,0><<<dim3(2, N1/128, BATCH), 256>>>(d0, SD0, Wd1, nullptr, xw, SXW,
        linv2, N1, nullptr, nullptr, nullptr, nullptr, nullptr, nullptr);
    spmmT<96,2><<<dim3(N1/2, 1, BATCH), dim3(96, 2)>>>(edge1, (long)N1*DEGMAX, deg1, N1,
                                                       xw, SXW, bd1, h1, SH1, 1, nullptr, nullptr);

    // 9. decoder GCN2 swapped: t = A0@unpool(h1) via masked ELL (C=96)
    spmmT<96,2><<<dim3(N0/2, 1, BATCH), dim3(96, 2)>>>(edge01, (long)N0*DEGMAX, deg01, N0,
                                                       h1, SH1, nullptr, xw, SXW, 0, nullptr, nullptr);
    gemmT<96,128,0,1><<<dim3(2, N0/128, BATCH), 256>>>(xw, SXW, Wd2, bd2, h, SH,
        nullptr, 0, nullptr, nullptr, nullptr, nullptr, nullptr, nullptr);

    // 10. output GCN + softplus
    gemmT<128,64,0,0><<<dim3(1, N0/128, BATCH), 256>>>(h, SH, Wout, nullptr, xw, SXW,
        nullptr, 0, nullptr, nullptr, nullptr, nullptr, nullptr, nullptr);
    spmmT<64,4><<<dim3(N0/4, 1, BATCH), dim3(64, 4)>>>(edge0, 0, deg0, 0,
                                                       xw, SXW, bout, out, (long)N0*FIN, 2, nullptr, nullptr);
}